// round 3
// baseline (speedup 1.0000x reference)
#include <cuda_runtime.h>
#include <cstdint>

// Shapes: L=16, N=128, C=10, D=13, H=128, HID=64, F=88
#define DINL __device__ __forceinline__

// ------------------------- device scratch -------------------------
__device__ __align__(16) float g_h1[4096 * 128];   // LSTM1 final hidden
__device__ __align__(16) float g_lo[2048 * 64];    // lo pre-BN
__device__ __align__(16) float g_part[128 * 64];   // BN1 partial sums
__device__ __align__(16) float g_part2[128 * 64];  // BN1 partial sumsq
__device__ float g_sc1[64], g_sh1[64];             // BN1 scale/shift
__device__ __align__(16) float g_Wcat[256 * 640];  // [Wlh|Wrh] repacked
__device__ float g_base[15 * 128];                 // per-step base vectors (a=0)
__device__ __align__(16) float g_h[2][128 * 128];  // tree h state (ping-pong)
__device__ __align__(16) float g_c[2][128 * 128];  // tree c state (ping-pong)
__device__ __align__(16) float g_P[128 * 640];     // tree projection per step
__device__ unsigned int g_bar_count;               // grid barrier (zero-init)
__device__ unsigned int g_bar_gen;

// ------------------------- helpers -------------------------
DINL float sigf(float x) { return __fdividef(1.f, 1.f + __expf(-x)); }
DINL float tanh_(float x) { return 2.f * sigf(2.f * x) - 1.f; }
DINL void fma2(unsigned long long& a, unsigned long long b, unsigned long long c) {
    asm("fma.rn.f32x2 %0, %1, %2, %0;" : "+l"(a) : "l"(b), "l"(c));
}
DINL unsigned long long dup2(float x) {
    unsigned long long r;
    asm("mov.b64 %0, {%1, %1};" : "=l"(r) : "f"(x));
    return r;
}
DINL float2 unp2(unsigned long long v) {
    float2 f;
    asm("mov.b64 {%0, %1}, %2;" : "=f"(f.x), "=f"(f.y) : "l"(v));
    return f;
}

// Software grid barrier (sense via generation counter). All blocks must be
// co-resident (40 blocks of 128 threads: trivially true on 148 SMs).
DINL void grid_barrier(unsigned int nb) {
    __syncthreads();
    if (threadIdx.x == 0) {
        __threadfence();
        unsigned int gen = *(volatile unsigned int*)&g_bar_gen;
        if (atomicAdd(&g_bar_count, 1u) == nb - 1) {
            atomicExch(&g_bar_count, 0u);
            __threadfence();
            atomicExch(&g_bar_gen, gen + 1u);
        } else {
            while (*(volatile unsigned int*)&g_bar_gen == gen) { __nanosleep(32); }
        }
        __threadfence();
    }
    __syncthreads();
}

// ---------------------------------------------------------------------------
// K1: LSTM1 over c_all = concat(cond1, cond2): 4096 rows x 10 steps, D=13->H=128
// Block = 128 threads = 4 warps; each warp owns 8 rows for the full sequence.
// z row layout: [0..127]=h, [128..140]=x_t. Gate cols: i,f,g,o at j*128.
// Lane owns hidden cols lane*4..lane*4+3 per gate (2 f32x2 pairs per gate).
// ---------------------------------------------------------------------------
__global__ void __launch_bounds__(128, 1) lstm1_kernel(
    const float* __restrict__ cond1, const float* __restrict__ cond2,
    const float* __restrict__ Wih, const float* __restrict__ Whh,
    const float* __restrict__ bias)
{
    __shared__ float z[32][144];
    const int tid = threadIdx.x, warp = tid >> 5, lane = tid & 31;
    const int lr0 = warp * 8;
    const int row0 = blockIdx.x * 32 + lr0;

    float4 zero4 = make_float4(0.f, 0.f, 0.f, 0.f);
#pragma unroll
    for (int r = 0; r < 8; r++) *(float4*)&z[lr0 + r][lane * 4] = zero4;

    float cst[8][4] = {};
    const float* src[8];
#pragma unroll
    for (int r = 0; r < 8; r++) {
        int gr = row0 + r;
        src[r] = (gr < 2048) ? (cond1 + (size_t)gr * 130)
                             : (cond2 + (size_t)(gr - 2048) * 130);
    }
    __syncwarp();

    const ulonglong2* Wh2 = (const ulonglong2*)Whh;  // row k = 128 ulonglong2
    const ulonglong2* Wi2 = (const ulonglong2*)Wih;

    for (int t = 0; t < 10; t++) {
        // load x_t for this warp's 8 rows (8*13 = 104 floats)
        for (int idx = lane; idx < 104; idx += 32) {
            int r = idx / 13, c = idx - r * 13;
            z[lr0 + r][128 + c] = src[r][t * 13 + c];
        }
        __syncwarp();

        unsigned long long acc[8][8];
#pragma unroll
        for (int j = 0; j < 4; j++) {
            ulonglong2 bb = *(const ulonglong2*)(bias + j * 128 + lane * 4);
#pragma unroll
            for (int r = 0; r < 8; r++) { acc[r][2 * j] = bb.x; acc[r][2 * j + 1] = bb.y; }
        }

        // h @ Whh
#pragma unroll 1
        for (int k = 0; k < 128; k++) {
            ulonglong2 w0 = Wh2[k * 128 + 0 * 32 + lane];
            ulonglong2 w1 = Wh2[k * 128 + 1 * 32 + lane];
            ulonglong2 w2 = Wh2[k * 128 + 2 * 32 + lane];
            ulonglong2 w3 = Wh2[k * 128 + 3 * 32 + lane];
#pragma unroll
            for (int r = 0; r < 8; r++) {
                unsigned long long a = dup2(z[lr0 + r][k]);
                fma2(acc[r][0], a, w0.x); fma2(acc[r][1], a, w0.y);
                fma2(acc[r][2], a, w1.x); fma2(acc[r][3], a, w1.y);
                fma2(acc[r][4], a, w2.x); fma2(acc[r][5], a, w2.y);
                fma2(acc[r][6], a, w3.x); fma2(acc[r][7], a, w3.y);
            }
        }
        // x @ Wih
#pragma unroll 1
        for (int k = 0; k < 13; k++) {
            ulonglong2 w0 = Wi2[k * 128 + 0 * 32 + lane];
            ulonglong2 w1 = Wi2[k * 128 + 1 * 32 + lane];
            ulonglong2 w2 = Wi2[k * 128 + 2 * 32 + lane];
            ulonglong2 w3 = Wi2[k * 128 + 3 * 32 + lane];
#pragma unroll
            for (int r = 0; r < 8; r++) {
                unsigned long long a = dup2(z[lr0 + r][128 + k]);
                fma2(acc[r][0], a, w0.x); fma2(acc[r][1], a, w0.y);
                fma2(acc[r][2], a, w1.x); fma2(acc[r][3], a, w1.y);
                fma2(acc[r][4], a, w2.x); fma2(acc[r][5], a, w2.y);
                fma2(acc[r][6], a, w3.x); fma2(acc[r][7], a, w3.y);
            }
        }
        __syncwarp();

#pragma unroll
        for (int r = 0; r < 8; r++) {
            float2 i01 = unp2(acc[r][0]), i23 = unp2(acc[r][1]);
            float2 f01 = unp2(acc[r][2]), f23 = unp2(acc[r][3]);
            float2 G01 = unp2(acc[r][4]), G23 = unp2(acc[r][5]);
            float2 o01 = unp2(acc[r][6]), o23 = unp2(acc[r][7]);
            float iv[4] = {i01.x, i01.y, i23.x, i23.y};
            float fv[4] = {f01.x, f01.y, f23.x, f23.y};
            float gv[4] = {G01.x, G01.y, G23.x, G23.y};
            float ov[4] = {o01.x, o01.y, o23.x, o23.y};
            float hv[4];
#pragma unroll
            for (int q = 0; q < 4; q++) {
                float c = sigf(fv[q]) * cst[r][q] + sigf(iv[q]) * tanh_(gv[q]);
                cst[r][q] = c;
                hv[q] = sigf(ov[q]) * tanh_(c);
            }
            *(float4*)&z[lr0 + r][lane * 4] = make_float4(hv[0], hv[1], hv[2], hv[3]);
        }
        __syncwarp();
    }

#pragma unroll
    for (int r = 0; r < 8; r++)
        *(float4*)&g_h1[(size_t)(row0 + r) * 128 + lane * 4] =
            *(float4*)&z[lr0 + r][lane * 4];
}

// ---------------------------------------------------------------------------
// K2: lo = 0.5*(relu(h1@Wc+bc)+relu(h2@Wc+bc)) (2048x64), 16 rows/block,
// plus deterministic per-block BN1 partial sums.
// ---------------------------------------------------------------------------
__global__ void __launch_bounds__(256) lo_kernel(const float* __restrict__ Wc,
                                                 const float* __restrict__ bc)
{
    __shared__ float ha[16][128], hb[16][128];
    __shared__ float red[256], red2[256];
    int tid = threadIdx.x, r0 = blockIdx.x * 16;
    for (int i = tid; i < 16 * 128; i += 256) {
        int r = i >> 7, h = i & 127;
        ha[r][h] = g_h1[(size_t)(r0 + r) * 128 + h];
        hb[r][h] = g_h1[(size_t)(2048 + r0 + r) * 128 + h];
    }
    __syncthreads();
    int j = tid & 63;
    float ps = 0.f, ps2 = 0.f;
#pragma unroll
    for (int rg = 0; rg < 4; rg++) {
        int r = (tid >> 6) + rg * 4;
        float s1 = bc[j], s2 = s1;
        for (int h = 0; h < 128; h++) {
            float w = Wc[h * 64 + j];
            s1 += ha[r][h] * w;
            s2 += hb[r][h] * w;
        }
        float v = 0.5f * (fmaxf(s1, 0.f) + fmaxf(s2, 0.f));
        g_lo[(size_t)(r0 + r) * 64 + j] = v;
        ps += v; ps2 += v * v;
    }
    red[tid] = ps; red2[tid] = ps2;
    __syncthreads();
    if (tid < 64) {
        for (int p = 1; p < 4; p++) { ps += red[tid + 64 * p]; ps2 += red2[tid + 64 * p]; }
        g_part[blockIdx.x * 64 + tid] = ps;
        g_part2[blockIdx.x * 64 + tid] = ps2;
    }
}

// K2b: finalize BN1 stats -> scale/shift
__global__ void __launch_bounds__(64) bn1_final_kernel(const float* __restrict__ g,
                                                       const float* __restrict__ be)
{
    int j = threadIdx.x;
    float s = 0.f, s2 = 0.f;
    for (int b = 0; b < 128; b++) { s += g_part[b * 64 + j]; s2 += g_part2[b * 64 + j]; }
    float m = s * (1.f / 2048.f);
    float v = s2 * (1.f / 2048.f) - m * m;
    float sc = g[j] * rsqrtf(v + 1e-5f);
    g_sc1[j] = sc;
    g_sh1[j] = be[j] - m * sc;
}

// ---------------------------------------------------------------------------
// K3: repack Wcat[h, g*128+k] = h<128 ? Wlh[g,h,k] : Wrh[g,h-128,k]
// ---------------------------------------------------------------------------
__global__ void __launch_bounds__(1024) wcat_kernel(const float* __restrict__ Wlh,
                                                    const float* __restrict__ Wrh)
{
    int i = blockIdx.x * 1024 + threadIdx.x;
    if (i >= 256 * 640) return;
    int h = i / 640, col = i - h * 640;
    int g = col >> 7, k = col & 127;
    g_Wcat[i] = (h < 128) ? Wlh[g * 16384 + h * 128 + k]
                          : Wrh[g * 16384 + (h - 128) * 128 + k];
}

// ---------------------------------------------------------------------------
// K4: prep = LSTM2 single step from zero state (blocks 0..127) + base vectors
// (blocks 128..142).  block 128 threads.
// ---------------------------------------------------------------------------
__global__ void __launch_bounds__(128) prep_kernel(
    const float* __restrict__ ops, const float* __restrict__ ext,
    const float* __restrict__ card, const float* __restrict__ Wih2,
    const float* __restrict__ b2, const float* __restrict__ Win,
    const float* __restrict__ bin_)
{
    __shared__ float x[88];
    int b = blockIdx.x, k = threadIdx.x;
    int row = (b < 128) ? (15 * 128 + b) : ((b - 128) * 128 + 0);
    if (k < 15)      x[k] = ops[row * 15 + k];
    else if (k < 22) x[k] = ext[row * 7 + (k - 15)];
    else if (k < 24) x[k] = card[row * 2 + (k - 22)];
    else if (k < 88) x[k] = g_lo[(size_t)row * 64 + (k - 24)] * g_sc1[k - 24] + g_sh1[k - 24];
    __syncthreads();

    if (b < 128) {
        float gi = b2[k], gg = b2[256 + k], go = b2[384 + k];
        for (int j = 0; j < 88; j++) {
            float xv = x[j];
            const float* w = Wih2 + j * 512;
            gi += xv * w[k];
            gg += xv * w[256 + k];
            go += xv * w[384 + k];
        }
        float c = sigf(gi) * tanh_(gg);  // sig(f)*c_prev = 0
        float h = sigf(go) * tanh_(c);
        g_h[0][b * 128 + k] = h;
        g_c[0][b * 128 + k] = c;
    } else {
        int l = b - 128;
        float s = bin_[k];
        for (int j = 0; j < 88; j++) s += x[j] * Win[j * 128 + k];
        g_base[(14 - l) * 128 + k] = s;
    }
}

// ---------------------------------------------------------------------------
// K5: fused tree scan — all 15 steps in one persistent kernel.
// grid (8,5) = 40 blocks, block 128.  Per step:
//   GEMM: P = gather([lh|rh])(128x256) @ Wcat(256x640); block (bx,g) does
//         16 rows x 128 cols (gate g).  Then grid barrier, then pointwise
//         cell update distributed over all 5120 threads, barrier, next step.
// ---------------------------------------------------------------------------
__global__ void __launch_bounds__(128) tree_kernel(const int* __restrict__ mapping,
                                                   const float* __restrict__ blh,
                                                   const float* __restrict__ brh)
{
    const unsigned int NB = 40;
    __shared__ float A[16][257];
    int tid = threadIdx.x, bx = blockIdx.x, g = blockIdx.y;
    int bid = blockIdx.y * 8 + blockIdx.x;

    for (int s = 0; s < 15; s++) {
        int lvl = 14 - s, p = s & 1;
        const float* __restrict__ hprev = g_h[p];

        // gather A = [lh|rh] rows for this block's 16 n
        for (int i = tid; i < 16 * 256; i += 128) {
            int r = i >> 8, h = i & 255;
            int n = bx * 16 + r;
            int mp = mapping[(lvl * 128 + n) * 2 + (h >> 7)];
            A[r][h] = (mp > 0) ? hprev[(mp - 1) * 128 + (h & 127)] : 0.f;
        }
        __syncthreads();

        // GEMM 16x128 tile for gate g
        int trp = tid >> 4, tc = tid & 15;
        int r0 = trp * 2;
        unsigned long long a00 = 0, a01 = 0, a02 = 0, a03 = 0;
        unsigned long long a10 = 0, a11 = 0, a12 = 0, a13 = 0;
        const float* W = g_Wcat + g * 128 + tc * 8;
#pragma unroll 4
        for (int k = 0; k < 256; k++) {
            unsigned long long v0 = dup2(A[r0][k]);
            unsigned long long v1 = dup2(A[r0 + 1][k]);
            const ulonglong2* wp = (const ulonglong2*)(W + (size_t)k * 640);
            ulonglong2 w0 = wp[0], w1 = wp[1];
            fma2(a00, v0, w0.x); fma2(a01, v0, w0.y); fma2(a02, v0, w1.x); fma2(a03, v0, w1.y);
            fma2(a10, v1, w0.x); fma2(a11, v1, w0.y); fma2(a12, v1, w1.x); fma2(a13, v1, w1.y);
        }
        int n0 = bx * 16 + r0;
        ulonglong2* P0 = (ulonglong2*)(g_P + (size_t)n0 * 640 + g * 128 + tc * 8);
        ulonglong2* P1 = (ulonglong2*)(g_P + (size_t)(n0 + 1) * 640 + g * 128 + tc * 8);
        P0[0] = make_ulonglong2(a00, a01); P0[1] = make_ulonglong2(a02, a03);
        P1[0] = make_ulonglong2(a10, a11); P1[1] = make_ulonglong2(a12, a13);

        grid_barrier(NB);

        // pointwise cell update over 128x128 elems, spread on 5120 threads
        for (int idx = bid * 128 + tid; idx < 16384; idx += 5120) {
            int n = idx >> 7, k = idx & 127;
            int mp0 = mapping[(lvl * 128 + n) * 2 + 0];
            int mp1 = mapping[(lvl * 128 + n) * 2 + 1];
            float lc = (mp0 > 0) ? g_c[p][(mp0 - 1) * 128 + k] : 0.f;
            float rc = (mp1 > 0) ? g_c[p][(mp1 - 1) * 128 + k] : 0.f;
            float bse = g_base[s * 128 + k];
            const float* P = g_P + (size_t)n * 640;
            float pre[5];
#pragma unroll
            for (int q = 0; q < 5; q++)
                pre[q] = bse + P[q * 128 + k] + blh[q * 128 + k] + brh[q * 128 + k];
            float i = sigf(pre[0]), lf = sigf(pre[1]), rf = sigf(pre[2]);
            float u = tanh_(pre[3]), o = sigf(pre[4]);
            float c = i * u + lf * lc + rf * rc;
            g_c[1 - p][n * 128 + k] = c;
            g_h[1 - p][n * 128 + k] = o * tanh_(c);
        }

        grid_barrier(NB);
    }
}

// ---------------------------------------------------------------------------
// K6: fused tail: BN2 -> t1 -> BN3 -> t2 -> sigmoid output.  One block, 256.
// ---------------------------------------------------------------------------
__global__ void __launch_bounds__(256) tail_kernel(
    const float* __restrict__ g2, const float* __restrict__ be2,
    const float* __restrict__ Wt1, const float* __restrict__ bt1,
    const float* __restrict__ g3, const float* __restrict__ be3,
    const float* __restrict__ Wt2, const float* __restrict__ bt2,
    const float* __restrict__ Wo, const float* __restrict__ bo,
    float* __restrict__ out)
{
    __shared__ float t1s[128 * 64];  // 32KB
    __shared__ float sc[128], sh[128];
    __shared__ float red[256], red2[256];
    int tid = threadIdx.x;

    // BN2 stats over g_h[1] (128x128)
    {
        int col = tid & 127, part = tid >> 7;
        float s = 0.f, s2 = 0.f;
        for (int r = part; r < 128; r += 2) {
            float v = g_h[1][r * 128 + col];
            s += v; s2 += v * v;
        }
        red[tid] = s; red2[tid] = s2;
        __syncthreads();
        if (tid < 128) {
            s = red[tid] + red[tid + 128];
            s2 = red2[tid] + red2[tid + 128];
            float m = s * (1.f / 128.f);
            float v = s2 * (1.f / 128.f) - m * m;
            float scl = g2[tid] * rsqrtf(v + 1e-5f);
            sc[tid] = scl;
            sh[tid] = be2[tid] - m * scl;
        }
        __syncthreads();
    }

    // t1 = relu(bn2(h) @ Wt1 + bt1)  (128x64)
    for (int o = tid; o < 8192; o += 256) {
        int n = o >> 6, j = o & 63;
        float acc = bt1[j];
        for (int h = 0; h < 128; h++)
            acc += (g_h[1][n * 128 + h] * sc[h] + sh[h]) * Wt1[h * 64 + j];
        t1s[o] = fmaxf(acc, 0.f);
    }
    __syncthreads();

    // BN3 stats over t1s (128x64)
    {
        int col = tid & 63, part = tid >> 6;
        float s = 0.f, s2 = 0.f;
        for (int r = part; r < 128; r += 4) {
            float v = t1s[r * 64 + col];
            s += v; s2 += v * v;
        }
        red[tid] = s; red2[tid] = s2;
        __syncthreads();
        if (tid < 64) {
            for (int p = 1; p < 4; p++) { s += red[tid + 64 * p]; s2 += red2[tid + 64 * p]; }
            float m = s * (1.f / 128.f);
            float v = s2 * (1.f / 128.f) - m * m;
            float scl = g3[tid] * rsqrtf(v + 1e-5f);
            sc[tid] = scl;
            sh[tid] = be3[tid] - m * scl;
        }
        __syncthreads();
    }

    // t2 = relu(bn3(t1)@Wt2+bt2); out = sigmoid(t2@Wo+bo)
    if (tid < 128) {
        int n = tid;
        float tn[64];
#pragma unroll
        for (int i = 0; i < 64; i++) tn[i] = t1s[n * 64 + i] * sc[i] + sh[i];
        float a = bo[0];
        for (int j = 0; j < 64; j++) {
            float s = bt2[j];
#pragma unroll
            for (int i = 0; i < 64; i++) s += tn[i] * Wt2[i * 64 + j];
            a += fmaxf(s, 0.f) * Wo[j];
        }
        out[n] = sigf(a);
    }
}

// ---------------------------------------------------------------------------
extern "C" void kernel_launch(void* const* d_in, const int* in_sizes, int n_in,
                              void* d_out, int out_size)
{
    const float* operators = (const float*)d_in[0];
    const float* extra     = (const float*)d_in[1];
    const float* card      = (const float*)d_in[2];
    const float* cond1     = (const float*)d_in[3];
    const float* cond2     = (const float*)d_in[4];
    const int*   mapping   = (const int*)  d_in[5];
    const float* Wih1      = (const float*)d_in[6];
    const float* Whh1      = (const float*)d_in[7];
    const float* b1        = (const float*)d_in[8];
    const float* Wc        = (const float*)d_in[9];
    const float* bc        = (const float*)d_in[10];
    const float* g1        = (const float*)d_in[11];
    const float* be1       = (const float*)d_in[12];
    const float* Wih2      = (const float*)d_in[13];
    // d_in[14] = Whh2: unused (single step from zero state)
    const float* b2        = (const float*)d_in[15];
    const float* Win       = (const float*)d_in[16];
    const float* bin_      = (const float*)d_in[17];
    const float* Wlh       = (const float*)d_in[18];
    const float* blh       = (const float*)d_in[19];
    const float* Wrh       = (const float*)d_in[20];
    const float* brh       = (const float*)d_in[21];
    const float* g2        = (const float*)d_in[22];
    const float* be2       = (const float*)d_in[23];
    const float* Wt1       = (const float*)d_in[24];
    const float* bt1       = (const float*)d_in[25];
    const float* g3        = (const float*)d_in[26];
    const float* be3       = (const float*)d_in[27];
    const float* Wt2       = (const float*)d_in[28];
    const float* bt2       = (const float*)d_in[29];
    const float* Wo        = (const float*)d_in[30];
    const float* bo        = (const float*)d_in[31];
    float* out = (float*)d_out;

    lstm1_kernel<<<128, 128>>>(cond1, cond2, Wih1, Whh1, b1);
    wcat_kernel<<<160, 1024>>>(Wlh, Wrh);
    lo_kernel<<<128, 256>>>(Wc, bc);
    bn1_final_kernel<<<1, 64>>>(g1, be1);
    prep_kernel<<<143, 128>>>(operators, extra, card, Wih2, b2, Win, bin_);
    tree_kernel<<<dim3(8, 5), 128>>>(mapping, blh, brh);
    tail_kernel<<<1, 256>>>(g2, be2, Wt1, bt1, g3, be3, Wt2, bt2, Wo, bo, out);
}

// round 4
// speedup vs baseline: 1.0319x; 1.0319x over previous
#include <cuda_runtime.h>
#include <cstdint>

// Shapes: L=16, N=128, C=10, D=13, H=128, HID=64, F=88
#define DINL __device__ __forceinline__

// ------------------------- device scratch -------------------------
__device__ __align__(16) float g_h1[4096 * 128];   // LSTM1 final hidden
__device__ __align__(16) float g_lo[2048 * 64];    // lo pre-BN
__device__ __align__(16) float g_part[128 * 64];   // BN1 partial sums
__device__ __align__(16) float g_part2[128 * 64];  // BN1 partial sumsq
__device__ float g_sc1[64], g_sh1[64];             // BN1 scale/shift
__device__ __align__(16) float g_Wcat[256 * 640];  // [Wlh|Wrh] repacked
__device__ __align__(16) float g_bb[5 * 128];      // blh+brh combined
__device__ __align__(16) float g_b1c[512];         // b1 copy (prefetch-friendly)
__device__ float g_base[15 * 128];                 // per-step base vectors (a=0)
__device__ __align__(16) float g_h[2][128 * 128];  // tree h state (ping-pong)
__device__ __align__(16) float g_c[2][128 * 128];  // tree c state (ping-pong)
__device__ __align__(16) float g_P[128 * 640];     // tree projection per step
__device__ unsigned int g_bar_count;               // grid barrier (zero-init)
__device__ unsigned int g_bar_gen;

// ------------------------- helpers -------------------------
DINL float sigf(float x) { return __fdividef(1.f, 1.f + __expf(-x)); }
DINL float tanh_(float x) { return 2.f * sigf(2.f * x) - 1.f; }
DINL void fma2(unsigned long long& a, unsigned long long b, unsigned long long c) {
    asm("fma.rn.f32x2 %0, %1, %2, %0;" : "+l"(a) : "l"(b), "l"(c));
}
DINL unsigned long long dup2(float x) {
    unsigned long long r;
    asm("mov.b64 %0, {%1, %1};" : "=l"(r) : "f"(x));
    return r;
}
DINL float2 unp2(unsigned long long v) {
    float2 f;
    asm("mov.b64 {%0, %1}, %2;" : "=f"(f.x), "=f"(f.y) : "l"(v));
    return f;
}

// Software grid barrier (sense via generation counter). 40 co-resident blocks.
DINL void grid_barrier(unsigned int nb) {
    __syncthreads();
    if (threadIdx.x == 0) {
        __threadfence();
        unsigned int gen = *(volatile unsigned int*)&g_bar_gen;
        if (atomicAdd(&g_bar_count, 1u) == nb - 1) {
            atomicExch(&g_bar_count, 0u);
            __threadfence();
            atomicExch(&g_bar_gen, gen + 1u);
        } else {
            while (*(volatile unsigned int*)&g_bar_gen == gen) { __nanosleep(32); }
        }
        __threadfence();
    }
    __syncthreads();
}

// ---------------------------------------------------------------------------
// P1: repack Wcat[h, g*128+k] = h<128 ? Wlh[g,h,k] : Wrh[g,h-128,k]
// ---------------------------------------------------------------------------
__global__ void __launch_bounds__(1024) wcat_kernel(const float* __restrict__ Wlh,
                                                    const float* __restrict__ Wrh)
{
    int i = blockIdx.x * 1024 + threadIdx.x;
    if (i >= 256 * 640) return;
    int h = i / 640, col = i - h * 640;
    int g = col >> 7, k = col & 127;
    g_Wcat[i] = (h < 128) ? Wlh[g * 16384 + h * 128 + k]
                          : Wrh[g * 16384 + (h - 128) * 128 + k];
}

// P2: combined tree bias
__global__ void __launch_bounds__(640) bb_kernel(const float* __restrict__ blh,
                                                 const float* __restrict__ brh)
{
    int i = threadIdx.x;
    g_bb[i] = blh[i] + brh[i];
}

// P3: b1 copy (also zeros barrier state for extra safety / determinism)
__global__ void __launch_bounds__(512) b1copy_kernel(const float* __restrict__ b1)
{
    int i = threadIdx.x;
    g_b1c[i] = b1[i];
    if (i == 0) { g_bar_count = 0u; }
}

// ---------------------------------------------------------------------------
// K1: LSTM1 over c_all = concat(cond1, cond2): 4096 rows x 10 steps, D=13->H=128
// Block = 256 threads = 8 warps; each warp owns 4 rows for the full sequence.
// z row layout: [0..127]=h, [128..140]=x_t. Gate cols: i,f,g,o at j*128.
// Lane owns hidden cols lane*4..lane*4+3 per gate (2 f32x2 pairs per gate).
// ---------------------------------------------------------------------------
__global__ void __launch_bounds__(256) lstm1_kernel(
    const float* __restrict__ cond1, const float* __restrict__ cond2,
    const float* __restrict__ Wih, const float* __restrict__ Whh)
{
    __shared__ float z[32][144];
    const int tid = threadIdx.x, warp = tid >> 5, lane = tid & 31;
    const int lr0 = warp * 4;
    const int row0 = blockIdx.x * 32 + lr0;

    float4 zero4 = make_float4(0.f, 0.f, 0.f, 0.f);
#pragma unroll
    for (int r = 0; r < 4; r++) *(float4*)&z[lr0 + r][lane * 4] = zero4;

    float cst[4][4] = {};
    const float* src[4];
#pragma unroll
    for (int r = 0; r < 4; r++) {
        int gr = row0 + r;
        src[r] = (gr < 2048) ? (cond1 + (size_t)gr * 130)
                             : (cond2 + (size_t)(gr - 2048) * 130);
    }
    __syncwarp();

    const ulonglong2* Wh2 = (const ulonglong2*)Whh;  // row k = 128 ulonglong2
    const ulonglong2* Wi2 = (const ulonglong2*)Wih;

    for (int t = 0; t < 10; t++) {
        // load x_t for this warp's 4 rows (4*13 = 52 floats)
        for (int idx = lane; idx < 52; idx += 32) {
            int r = idx / 13, c = idx - r * 13;
            z[lr0 + r][128 + c] = src[r][t * 13 + c];
        }
        __syncwarp();

        unsigned long long acc[4][8];
#pragma unroll
        for (int j = 0; j < 4; j++) {
            ulonglong2 bb = *(const ulonglong2*)(g_b1c + j * 128 + lane * 4);
#pragma unroll
            for (int r = 0; r < 4; r++) { acc[r][2 * j] = bb.x; acc[r][2 * j + 1] = bb.y; }
        }

        // h @ Whh
#pragma unroll 2
        for (int k = 0; k < 128; k++) {
            ulonglong2 w0 = Wh2[k * 128 + 0 * 32 + lane];
            ulonglong2 w1 = Wh2[k * 128 + 1 * 32 + lane];
            ulonglong2 w2 = Wh2[k * 128 + 2 * 32 + lane];
            ulonglong2 w3 = Wh2[k * 128 + 3 * 32 + lane];
#pragma unroll
            for (int r = 0; r < 4; r++) {
                unsigned long long a = dup2(z[lr0 + r][k]);
                fma2(acc[r][0], a, w0.x); fma2(acc[r][1], a, w0.y);
                fma2(acc[r][2], a, w1.x); fma2(acc[r][3], a, w1.y);
                fma2(acc[r][4], a, w2.x); fma2(acc[r][5], a, w2.y);
                fma2(acc[r][6], a, w3.x); fma2(acc[r][7], a, w3.y);
            }
        }
        // x @ Wih
#pragma unroll 2
        for (int k = 0; k < 13; k++) {
            ulonglong2 w0 = Wi2[k * 128 + 0 * 32 + lane];
            ulonglong2 w1 = Wi2[k * 128 + 1 * 32 + lane];
            ulonglong2 w2 = Wi2[k * 128 + 2 * 32 + lane];
            ulonglong2 w3 = Wi2[k * 128 + 3 * 32 + lane];
#pragma unroll
            for (int r = 0; r < 4; r++) {
                unsigned long long a = dup2(z[lr0 + r][128 + k]);
                fma2(acc[r][0], a, w0.x); fma2(acc[r][1], a, w0.y);
                fma2(acc[r][2], a, w1.x); fma2(acc[r][3], a, w1.y);
                fma2(acc[r][4], a, w2.x); fma2(acc[r][5], a, w2.y);
                fma2(acc[r][6], a, w3.x); fma2(acc[r][7], a, w3.y);
            }
        }
        __syncwarp();

#pragma unroll
        for (int r = 0; r < 4; r++) {
            float2 i01 = unp2(acc[r][0]), i23 = unp2(acc[r][1]);
            float2 f01 = unp2(acc[r][2]), f23 = unp2(acc[r][3]);
            float2 G01 = unp2(acc[r][4]), G23 = unp2(acc[r][5]);
            float2 o01 = unp2(acc[r][6]), o23 = unp2(acc[r][7]);
            float iv[4] = {i01.x, i01.y, i23.x, i23.y};
            float fv[4] = {f01.x, f01.y, f23.x, f23.y};
            float gv[4] = {G01.x, G01.y, G23.x, G23.y};
            float ov[4] = {o01.x, o01.y, o23.x, o23.y};
            float hv[4];
#pragma unroll
            for (int q = 0; q < 4; q++) {
                float c = sigf(fv[q]) * cst[r][q] + sigf(iv[q]) * tanh_(gv[q]);
                cst[r][q] = c;
                hv[q] = sigf(ov[q]) * tanh_(c);
            }
            *(float4*)&z[lr0 + r][lane * 4] = make_float4(hv[0], hv[1], hv[2], hv[3]);
        }
        __syncwarp();
    }

#pragma unroll
    for (int r = 0; r < 4; r++)
        *(float4*)&g_h1[(size_t)(row0 + r) * 128 + lane * 4] =
            *(float4*)&z[lr0 + r][lane * 4];
}

// ---------------------------------------------------------------------------
// K2: lo = 0.5*(relu(h1@Wc+bc)+relu(h2@Wc+bc)) (2048x64), 16 rows/block,
// plus deterministic per-block BN1 partial sums.
// ---------------------------------------------------------------------------
__global__ void __launch_bounds__(256) lo_kernel(const float* __restrict__ Wc,
                                                 const float* __restrict__ bc)
{
    __shared__ float ha[16][128], hb[16][128];
    __shared__ float red[256], red2[256];
    int tid = threadIdx.x, r0 = blockIdx.x * 16;
    for (int i = tid; i < 16 * 128; i += 256) {
        int r = i >> 7, h = i & 127;
        ha[r][h] = g_h1[(size_t)(r0 + r) * 128 + h];
        hb[r][h] = g_h1[(size_t)(2048 + r0 + r) * 128 + h];
    }
    __syncthreads();
    int j = tid & 63;
    float ps = 0.f, ps2 = 0.f;
#pragma unroll
    for (int rg = 0; rg < 4; rg++) {
        int r = (tid >> 6) + rg * 4;
        float s1 = bc[j], s2 = s1;
        for (int h = 0; h < 128; h++) {
            float w = Wc[h * 64 + j];
            s1 += ha[r][h] * w;
            s2 += hb[r][h] * w;
        }
        float v = 0.5f * (fmaxf(s1, 0.f) + fmaxf(s2, 0.f));
        g_lo[(size_t)(r0 + r) * 64 + j] = v;
        ps += v; ps2 += v * v;
    }
    red[tid] = ps; red2[tid] = ps2;
    __syncthreads();
    if (tid < 64) {
        for (int p = 1; p < 4; p++) { ps += red[tid + 64 * p]; ps2 += red2[tid + 64 * p]; }
        g_part[blockIdx.x * 64 + tid] = ps;
        g_part2[blockIdx.x * 64 + tid] = ps2;
    }
}

// K2b: finalize BN1 stats -> scale/shift
__global__ void __launch_bounds__(64) bn1_final_kernel(const float* __restrict__ g,
                                                       const float* __restrict__ be)
{
    int j = threadIdx.x;
    float s = 0.f, s2 = 0.f;
    for (int b = 0; b < 128; b++) { s += g_part[b * 64 + j]; s2 += g_part2[b * 64 + j]; }
    float m = s * (1.f / 2048.f);
    float v = s2 * (1.f / 2048.f) - m * m;
    float sc = g[j] * rsqrtf(v + 1e-5f);
    g_sc1[j] = sc;
    g_sh1[j] = be[j] - m * sc;
}

// ---------------------------------------------------------------------------
// K4: prep = LSTM2 single step from zero state (blocks 0..127) + base vectors
// (blocks 128..142).  block 128 threads.
// ---------------------------------------------------------------------------
__global__ void __launch_bounds__(128) prep_kernel(
    const float* __restrict__ ops, const float* __restrict__ ext,
    const float* __restrict__ card, const float* __restrict__ Wih2,
    const float* __restrict__ b2, const float* __restrict__ Win,
    const float* __restrict__ bin_)
{
    __shared__ float x[88];
    int b = blockIdx.x, k = threadIdx.x;
    int row = (b < 128) ? (15 * 128 + b) : ((b - 128) * 128 + 0);
    if (k < 15)      x[k] = ops[row * 15 + k];
    else if (k < 22) x[k] = ext[row * 7 + (k - 15)];
    else if (k < 24) x[k] = card[row * 2 + (k - 22)];
    else if (k < 88) x[k] = g_lo[(size_t)row * 64 + (k - 24)] * g_sc1[k - 24] + g_sh1[k - 24];
    __syncthreads();

    if (b < 128) {
        float gi = b2[k], gg = b2[256 + k], go = b2[384 + k];
        for (int j = 0; j < 88; j++) {
            float xv = x[j];
            const float* w = Wih2 + j * 512;
            gi += xv * w[k];
            gg += xv * w[256 + k];
            go += xv * w[384 + k];
        }
        float c = sigf(gi) * tanh_(gg);  // sig(f)*c_prev = 0
        float h = sigf(go) * tanh_(c);
        g_h[0][b * 128 + k] = h;
        g_c[0][b * 128 + k] = c;
    } else {
        int l = b - 128;
        float s = bin_[k];
        for (int j = 0; j < 88; j++) s += x[j] * Win[j * 128 + k];
        g_base[(14 - l) * 128 + k] = s;
    }
}

// ---------------------------------------------------------------------------
// K5: fused tree scan — all 15 steps in one persistent kernel.
// grid (8,5) = 40 blocks, block 128.
// ---------------------------------------------------------------------------
__global__ void __launch_bounds__(128) tree_kernel(const int* __restrict__ mapping)
{
    const unsigned int NB = 40;
    __shared__ float A[16][257];
    int tid = threadIdx.x, bx = blockIdx.x, g = blockIdx.y;
    int bid = blockIdx.y * 8 + blockIdx.x;

    for (int s = 0; s < 15; s++) {
        int lvl = 14 - s, p = s & 1;
        const float* __restrict__ hprev = g_h[p];

        // gather A = [lh|rh] rows for this block's 16 n
        for (int i = tid; i < 16 * 256; i += 128) {
            int r = i >> 8, h = i & 255;
            int n = bx * 16 + r;
            int mp = mapping[(lvl * 128 + n) * 2 + (h >> 7)];
            A[r][h] = (mp > 0) ? hprev[(mp - 1) * 128 + (h & 127)] : 0.f;
        }
        __syncthreads();

        // GEMM 16x128 tile for gate g
        int trp = tid >> 4, tc = tid & 15;
        int r0 = trp * 2;
        unsigned long long a00 = 0, a01 = 0, a02 = 0, a03 = 0;
        unsigned long long a10 = 0, a11 = 0, a12 = 0, a13 = 0;
        const float* W = g_Wcat + g * 128 + tc * 8;
#pragma unroll 4
        for (int k = 0; k < 256; k++) {
            unsigned long long v0 = dup2(A[r0][k]);
            unsigned long long v1 = dup2(A[r0 + 1][k]);
            const ulonglong2* wp = (const ulonglong2*)(W + (size_t)k * 640);
            ulonglong2 w0 = wp[0], w1 = wp[1];
            fma2(a00, v0, w0.x); fma2(a01, v0, w0.y); fma2(a02, v0, w1.x); fma2(a03, v0, w1.y);
            fma2(a10, v1, w0.x); fma2(a11, v1, w0.y); fma2(a12, v1, w1.x); fma2(a13, v1, w1.y);
        }
        int n0 = bx * 16 + r0;
        ulonglong2* P0 = (ulonglong2*)(g_P + (size_t)n0 * 640 + g * 128 + tc * 8);
        ulonglong2* P1 = (ulonglong2*)(g_P + (size_t)(n0 + 1) * 640 + g * 128 + tc * 8);
        P0[0] = make_ulonglong2(a00, a01); P0[1] = make_ulonglong2(a02, a03);
        P1[0] = make_ulonglong2(a10, a11); P1[1] = make_ulonglong2(a12, a13);

        grid_barrier(NB);

        // pointwise cell update over 128x128 elems, spread on 5120 threads
        for (int idx = bid * 128 + tid; idx < 16384; idx += 5120) {
            int n = idx >> 7, k = idx & 127;
            int mp0 = mapping[(lvl * 128 + n) * 2 + 0];
            int mp1 = mapping[(lvl * 128 + n) * 2 + 1];
            float lc = (mp0 > 0) ? g_c[p][(mp0 - 1) * 128 + k] : 0.f;
            float rc = (mp1 > 0) ? g_c[p][(mp1 - 1) * 128 + k] : 0.f;
            float bse = g_base[s * 128 + k];
            const float* P = g_P + (size_t)n * 640;
            float pre[5];
#pragma unroll
            for (int q = 0; q < 5; q++)
                pre[q] = bse + P[q * 128 + k] + g_bb[q * 128 + k];
            float i = sigf(pre[0]), lf = sigf(pre[1]), rf = sigf(pre[2]);
            float u = tanh_(pre[3]), o = sigf(pre[4]);
            float c = i * u + lf * lc + rf * rc;
            g_c[1 - p][n * 128 + k] = c;
            g_h[1 - p][n * 128 + k] = o * tanh_(c);
        }

        grid_barrier(NB);
    }
}

// ---------------------------------------------------------------------------
// K6: fused tail: BN2 -> t1 -> BN3 -> t2 -> sigmoid output.  One block, 256.
// ---------------------------------------------------------------------------
__global__ void __launch_bounds__(256) tail_kernel(
    const float* __restrict__ g2, const float* __restrict__ be2,
    const float* __restrict__ Wt1, const float* __restrict__ bt1,
    const float* __restrict__ g3, const float* __restrict__ be3,
    const float* __restrict__ Wt2, const float* __restrict__ bt2,
    const float* __restrict__ Wo, const float* __restrict__ bo,
    float* __restrict__ out)
{
    __shared__ float t1s[128 * 64];  // 32KB
    __shared__ float sc[128], sh[128];
    __shared__ float red[256], red2[256];
    int tid = threadIdx.x;

    // BN2 stats over g_h[1] (128x128)
    {
        int col = tid & 127, part = tid >> 7;
        float s = 0.f, s2 = 0.f;
        for (int r = part; r < 128; r += 2) {
            float v = g_h[1][r * 128 + col];
            s += v; s2 += v * v;
        }
        red[tid] = s; red2[tid] = s2;
        __syncthreads();
        if (tid < 128) {
            s = red[tid] + red[tid + 128];
            s2 = red2[tid] + red2[tid + 128];
            float m = s * (1.f / 128.f);
            float v = s2 * (1.f / 128.f) - m * m;
            float scl = g2[tid] * rsqrtf(v + 1e-5f);
            sc[tid] = scl;
            sh[tid] = be2[tid] - m * scl;
        }
        __syncthreads();
    }

    // t1 = relu(bn2(h) @ Wt1 + bt1)  (128x64)
    for (int o = tid; o < 8192; o += 256) {
        int n = o >> 6, j = o & 63;
        float acc = bt1[j];
        for (int h = 0; h < 128; h++)
            acc += (g_h[1][n * 128 + h] * sc[h] + sh[h]) * Wt1[h * 64 + j];
        t1s[o] = fmaxf(acc, 0.f);
    }
    __syncthreads();

    // BN3 stats over t1s (128x64)
    {
        int col = tid & 63, part = tid >> 6;
        float s = 0.f, s2 = 0.f;
        for (int r = part; r < 128; r += 4) {
            float v = t1s[r * 64 + col];
            s += v; s2 += v * v;
        }
        red[tid] = s; red2[tid] = s2;
        __syncthreads();
        if (tid < 64) {
            for (int p = 1; p < 4; p++) { s += red[tid + 64 * p]; s2 += red2[tid + 64 * p]; }
            float m = s * (1.f / 128.f);
            float v = s2 * (1.f / 128.f) - m * m;
            float scl = g3[tid] * rsqrtf(v + 1e-5f);
            sc[tid] = scl;
            sh[tid] = be3[tid] - m * scl;
        }
        __syncthreads();
    }

    // t2 = relu(bn3(t1)@Wt2+bt2); out = sigmoid(t2@Wo+bo)
    if (tid < 128) {
        int n = tid;
        float tn[64];
#pragma unroll
        for (int i = 0; i < 64; i++) tn[i] = t1s[n * 64 + i] * sc[i] + sh[i];
        float a = bo[0];
        for (int j = 0; j < 64; j++) {
            float s = bt2[j];
#pragma unroll
            for (int i = 0; i < 64; i++) s += tn[i] * Wt2[i * 64 + j];
            a += fmaxf(s, 0.f) * Wo[j];
        }
        out[n] = sigf(a);
    }
}

// ---------------------------------------------------------------------------
extern "C" void kernel_launch(void* const* d_in, const int* in_sizes, int n_in,
                              void* d_out, int out_size)
{
    const float* operators = (const float*)d_in[0];
    const float* extra     = (const float*)d_in[1];
    const float* card      = (const float*)d_in[2];
    const float* cond1     = (const float*)d_in[3];
    const float* cond2     = (const float*)d_in[4];
    const int*   mapping   = (const int*)  d_in[5];
    const float* Wih1      = (const float*)d_in[6];
    const float* Whh1      = (const float*)d_in[7];
    const float* b1        = (const float*)d_in[8];
    const float* Wc        = (const float*)d_in[9];
    const float* bc        = (const float*)d_in[10];
    const float* g1        = (const float*)d_in[11];
    const float* be1       = (const float*)d_in[12];
    const float* Wih2      = (const float*)d_in[13];
    // d_in[14] = Whh2: unused (single step from zero state)
    const float* b2        = (const float*)d_in[15];
    const float* Win       = (const float*)d_in[16];
    const float* bin_      = (const float*)d_in[17];
    const float* Wlh       = (const float*)d_in[18];
    const float* blh       = (const float*)d_in[19];
    const float* Wrh       = (const float*)d_in[20];
    const float* brh       = (const float*)d_in[21];
    const float* g2        = (const float*)d_in[22];
    const float* be2       = (const float*)d_in[23];
    const float* Wt1       = (const float*)d_in[24];
    const float* bt1       = (const float*)d_in[25];
    const float* g3        = (const float*)d_in[26];
    const float* be3       = (const float*)d_in[27];
    const float* Wt2       = (const float*)d_in[28];
    const float* bt2       = (const float*)d_in[29];
    const float* Wo        = (const float*)d_in[30];
    const float* bo        = (const float*)d_in[31];
    float* out = (float*)d_out;

    // ordering: lstm1 is our launch idx 3 so ncu (-s 5, 2 harness launches
    // ahead of us) profiles it.
    wcat_kernel<<<160, 1024>>>(Wlh, Wrh);
    bb_kernel<<<1, 640>>>(blh, brh);
    b1copy_kernel<<<1, 512>>>(b1);
    lstm1_kernel<<<128, 256>>>(cond1, cond2, Wih1, Whh1);
    lo_kernel<<<128, 256>>>(Wc, bc);
    bn1_final_kernel<<<1, 64>>>(g1, be1);
    prep_kernel<<<143, 128>>>(operators, extra, card, Wih2, b2, Win, bin_);
    tree_kernel<<<dim3(8, 5), 128>>>(mapping);
    tail_kernel<<<1, 256>>>(g2, be2, Wt1, bt1, g3, be3, Wt2, bt2, Wo, bo, out);
}

// round 5
// speedup vs baseline: 1.6478x; 1.5968x over previous
#include <cuda_runtime.h>
#include <cstdint>

// Shapes: L=16, N=128, C=10, D=13, H=128, HID=64, F=88
#define DINL __device__ __forceinline__

// ------------------------- device scratch -------------------------
__device__ __align__(16) float g_h1[4096 * 128];   // LSTM1 final hidden
__device__ __align__(16) float g_lo[2048 * 64];    // lo pre-BN
__device__ __align__(16) float g_part[128 * 64];   // BN1 partial sums
__device__ __align__(16) float g_part2[128 * 64];  // BN1 partial sumsq
__device__ float g_sc1[64], g_sh1[64];             // BN1 scale/shift
__device__ __align__(16) float g_Wcat[256 * 640];  // [Wlh|Wrh] repacked
__device__ __align__(16) float g_bb[5 * 128];      // blh+brh combined
__device__ __align__(16) float g_b1c[512];         // b1 copy
__device__ float g_base[15 * 128];                 // per-step base vectors (a=0)
__device__ __align__(16) float g_h[2][128 * 128];  // tree h state (ping-pong)
__device__ __align__(16) float g_c[2][128 * 128];  // tree c state (ping-pong)
__device__ __align__(16) float g_P[128 * 640];     // tree projection per step
__device__ unsigned int g_bar_count;               // grid barrier (zero-init)
__device__ unsigned int g_bar_gen;

// ------------------------- helpers -------------------------
DINL float sigf(float x) { return __fdividef(1.f, 1.f + __expf(-x)); }
DINL float tanh_(float x) { return 2.f * sigf(2.f * x) - 1.f; }
DINL void fma2(unsigned long long& a, unsigned long long b, unsigned long long c) {
    asm("fma.rn.f32x2 %0, %1, %2, %0;" : "+l"(a) : "l"(b), "l"(c));
}
DINL void add2(unsigned long long& a, unsigned long long b) {
    asm("add.rn.f32x2 %0, %0, %1;" : "+l"(a) : "l"(b));
}
DINL unsigned long long dup2(float x) {
    unsigned long long r;
    asm("mov.b64 %0, {%1, %1};" : "=l"(r) : "f"(x));
    return r;
}
DINL float2 unp2(unsigned long long v) {
    float2 f;
    asm("mov.b64 {%0, %1}, %2;" : "=f"(f.x), "=f"(f.y) : "l"(v));
    return f;
}
DINL void cpasync16(uint32_t dst, const void* src) {
    asm volatile("cp.async.ca.shared.global [%0], [%1], 16;" :: "r"(dst), "l"(src) : "memory");
}
DINL void cp_commit() { asm volatile("cp.async.commit_group;" ::: "memory"); }
DINL void cp_wait1() { asm volatile("cp.async.wait_group 1;" ::: "memory"); }

// Software grid barrier (sense via generation counter). 40 co-resident blocks.
DINL void grid_barrier(unsigned int nb) {
    __syncthreads();
    if (threadIdx.x == 0) {
        __threadfence();
        unsigned int gen = *(volatile unsigned int*)&g_bar_gen;
        if (atomicAdd(&g_bar_count, 1u) == nb - 1) {
            atomicExch(&g_bar_count, 0u);
            __threadfence();
            atomicExch(&g_bar_gen, gen + 1u);
        } else {
            while (*(volatile unsigned int*)&g_bar_gen == gen) {}
        }
        __threadfence();
    }
    __syncthreads();
}

// ---------------------------------------------------------------------------
// P1: repack Wcat[h, g*128+k] = h<128 ? Wlh[g,h,k] : Wrh[g,h-128,k]
// ---------------------------------------------------------------------------
__global__ void __launch_bounds__(1024) wcat_kernel(const float* __restrict__ Wlh,
                                                    const float* __restrict__ Wrh)
{
    int i = blockIdx.x * 1024 + threadIdx.x;
    if (i >= 256 * 640) return;
    int h = i / 640, col = i - h * 640;
    int g = col >> 7, k = col & 127;
    g_Wcat[i] = (h < 128) ? Wlh[g * 16384 + h * 128 + k]
                          : Wrh[g * 16384 + (h - 128) * 128 + k];
}

// P2: combined tree bias
__global__ void __launch_bounds__(640) bb_kernel(const float* __restrict__ blh,
                                                 const float* __restrict__ brh)
{
    int i = threadIdx.x;
    g_bb[i] = blh[i] + brh[i];
}

// P3: b1 copy + barrier reset
__global__ void __launch_bounds__(512) b1copy_kernel(const float* __restrict__ b1)
{
    int i = threadIdx.x;
    g_b1c[i] = b1[i];
    if (i == 0) { g_bar_count = 0u; }
}

// ---------------------------------------------------------------------------
// K1: LSTM1 over c_all = concat(cond1, cond2): 4096 rows x 10 steps, D=13->H=128
// Block = 256 threads = 8 warps; each warp owns 4 rows for the full sequence.
// Weights staged into smem via cp.async (double-buffered 16-k tiles); Wih
// resident in smem for all steps.  Dynamic smem layout (floats):
//   z[32][144]  (4608) | wihs 13*512 (6656) | ws 2*16*512 (16384)  = 110592 B
// ---------------------------------------------------------------------------
DINL void stage_tile(uint32_t ws_addr, const float* Whh, int tile, int buf, int tid) {
    const char* src = (const char*)(Whh + tile * 8192) + tid * 16;
    uint32_t dst = ws_addr + buf * 32768 + tid * 16;
#pragma unroll
    for (int i = 0; i < 8; i++)
        cpasync16(dst + i * 4096, src + i * 4096);
}

__global__ void __launch_bounds__(256) lstm1_kernel(
    const float* __restrict__ cond1, const float* __restrict__ cond2,
    const float* __restrict__ Wih, const float* __restrict__ Whh)
{
    extern __shared__ float smem[];
    float (*z)[144] = (float (*)[144])smem;
    float* wihs = smem + 4608;
    float* ws   = smem + 4608 + 6656;
    uint32_t wih_addr = (uint32_t)__cvta_generic_to_shared(wihs);
    uint32_t ws_addr  = (uint32_t)__cvta_generic_to_shared(ws);

    const int tid = threadIdx.x, warp = tid >> 5, lane = tid & 31;
    const int lr0 = warp * 4;
    const int row0 = blockIdx.x * 32 + lr0;

    // stage Wih once (1664 x 16B)
    for (int i = tid; i < 1664; i += 256)
        cpasync16(wih_addr + i * 16, (const char*)Wih + i * 16);
    cp_commit();
    // prefetch Whh tile 0
    stage_tile(ws_addr, Whh, 0, 0, tid);
    cp_commit();

    float4 zero4 = make_float4(0.f, 0.f, 0.f, 0.f);
#pragma unroll
    for (int r = 0; r < 4; r++) *(float4*)&z[lr0 + r][lane * 4] = zero4;

    float cst[4][4] = {};
    const float* src[4];
#pragma unroll
    for (int r = 0; r < 4; r++) {
        int gr = row0 + r;
        src[r] = (gr < 2048) ? (cond1 + (size_t)gr * 130)
                             : (cond2 + (size_t)(gr - 2048) * 130);
    }

    unsigned long long bias[8];
#pragma unroll
    for (int j = 0; j < 4; j++) {
        ulonglong2 bb = *(const ulonglong2*)(g_b1c + j * 128 + lane * 4);
        bias[2 * j] = bb.x; bias[2 * j + 1] = bb.y;
    }
    __syncwarp();

    for (int t = 0; t < 10; t++) {
        // load x_t for this warp's 4 rows (4*13 = 52 floats)
        for (int idx = lane; idx < 52; idx += 32) {
            int r = idx / 13, c = idx - r * 13;
            z[lr0 + r][128 + c] = src[r][t * 13 + c];
        }
        __syncwarp();

        unsigned long long acc[4][8];
#pragma unroll
        for (int r = 0; r < 4; r++)
#pragma unroll
            for (int j = 0; j < 8; j++) acc[r][j] = bias[j];

        // h @ Whh via pipelined smem tiles (8 tiles of 16 k)
        for (int kt = 0; kt < 8; kt++) {
            stage_tile(ws_addr, Whh, (kt + 1) & 7, (kt + 1) & 1, tid);
            cp_commit();
            cp_wait1();
            __syncthreads();
            const ulonglong2* W = (const ulonglong2*)(ws + (kt & 1) * 8192);
            const float* zk = &z[0][0];
#pragma unroll 4
            for (int kk = 0; kk < 16; kk++) {
                ulonglong2 w0 = W[kk * 128 + 0 * 32 + lane];
                ulonglong2 w1 = W[kk * 128 + 1 * 32 + lane];
                ulonglong2 w2 = W[kk * 128 + 2 * 32 + lane];
                ulonglong2 w3 = W[kk * 128 + 3 * 32 + lane];
                int k = kt * 16 + kk;
#pragma unroll
                for (int r = 0; r < 4; r++) {
                    unsigned long long a = dup2(zk[(lr0 + r) * 144 + k]);
                    fma2(acc[r][0], a, w0.x); fma2(acc[r][1], a, w0.y);
                    fma2(acc[r][2], a, w1.x); fma2(acc[r][3], a, w1.y);
                    fma2(acc[r][4], a, w2.x); fma2(acc[r][5], a, w2.y);
                    fma2(acc[r][6], a, w3.x); fma2(acc[r][7], a, w3.y);
                }
            }
            __syncthreads();
        }

        // x @ Wih from resident smem
        {
            const ulonglong2* Wx = (const ulonglong2*)wihs;
#pragma unroll 4
            for (int k = 0; k < 13; k++) {
                ulonglong2 w0 = Wx[k * 128 + 0 * 32 + lane];
                ulonglong2 w1 = Wx[k * 128 + 1 * 32 + lane];
                ulonglong2 w2 = Wx[k * 128 + 2 * 32 + lane];
                ulonglong2 w3 = Wx[k * 128 + 3 * 32 + lane];
#pragma unroll
                for (int r = 0; r < 4; r++) {
                    unsigned long long a = dup2(z[lr0 + r][128 + k]);
                    fma2(acc[r][0], a, w0.x); fma2(acc[r][1], a, w0.y);
                    fma2(acc[r][2], a, w1.x); fma2(acc[r][3], a, w1.y);
                    fma2(acc[r][4], a, w2.x); fma2(acc[r][5], a, w2.y);
                    fma2(acc[r][6], a, w3.x); fma2(acc[r][7], a, w3.y);
                }
            }
        }
        __syncwarp();

#pragma unroll
        for (int r = 0; r < 4; r++) {
            float2 i01 = unp2(acc[r][0]), i23 = unp2(acc[r][1]);
            float2 f01 = unp2(acc[r][2]), f23 = unp2(acc[r][3]);
            float2 G01 = unp2(acc[r][4]), G23 = unp2(acc[r][5]);
            float2 o01 = unp2(acc[r][6]), o23 = unp2(acc[r][7]);
            float iv[4] = {i01.x, i01.y, i23.x, i23.y};
            float fv[4] = {f01.x, f01.y, f23.x, f23.y};
            float gv[4] = {G01.x, G01.y, G23.x, G23.y};
            float ov[4] = {o01.x, o01.y, o23.x, o23.y};
            float hv[4];
#pragma unroll
            for (int q = 0; q < 4; q++) {
                float c = sigf(fv[q]) * cst[r][q] + sigf(iv[q]) * tanh_(gv[q]);
                cst[r][q] = c;
                hv[q] = sigf(ov[q]) * tanh_(c);
            }
            *(float4*)&z[lr0 + r][lane * 4] = make_float4(hv[0], hv[1], hv[2], hv[3]);
        }
        __syncwarp();
    }

#pragma unroll
    for (int r = 0; r < 4; r++)
        *(float4*)&g_h1[(size_t)(row0 + r) * 128 + lane * 4] =
            *(float4*)&z[lr0 + r][lane * 4];
}

// ---------------------------------------------------------------------------
// K2: lo = 0.5*(relu(h1@Wc+bc)+relu(h2@Wc+bc)) (2048x64), 16 rows/block,
// plus deterministic per-block BN1 partial sums.
// ---------------------------------------------------------------------------
__global__ void __launch_bounds__(256) lo_kernel(const float* __restrict__ Wc,
                                                 const float* __restrict__ bc)
{
    __shared__ float ha[16][128], hb[16][128];
    __shared__ float red[256], red2[256];
    int tid = threadIdx.x, r0 = blockIdx.x * 16;
    for (int i = tid; i < 16 * 128; i += 256) {
        int r = i >> 7, h = i & 127;
        ha[r][h] = g_h1[(size_t)(r0 + r) * 128 + h];
        hb[r][h] = g_h1[(size_t)(2048 + r0 + r) * 128 + h];
    }
    __syncthreads();
    int j = tid & 63;
    float ps = 0.f, ps2 = 0.f;
#pragma unroll
    for (int rg = 0; rg < 4; rg++) {
        int r = (tid >> 6) + rg * 4;
        float s1 = bc[j], s2 = s1;
        for (int h = 0; h < 128; h++) {
            float w = Wc[h * 64 + j];
            s1 += ha[r][h] * w;
            s2 += hb[r][h] * w;
        }
        float v = 0.5f * (fmaxf(s1, 0.f) + fmaxf(s2, 0.f));
        g_lo[(size_t)(r0 + r) * 64 + j] = v;
        ps += v; ps2 += v * v;
    }
    red[tid] = ps; red2[tid] = ps2;
    __syncthreads();
    if (tid < 64) {
        for (int p = 1; p < 4; p++) { ps += red[tid + 64 * p]; ps2 += red2[tid + 64 * p]; }
        g_part[blockIdx.x * 64 + tid] = ps;
        g_part2[blockIdx.x * 64 + tid] = ps2;
    }
}

// K2b: finalize BN1 stats -> scale/shift (256 threads, 4-way partial)
__global__ void __launch_bounds__(256) bn1_final_kernel(const float* __restrict__ g,
                                                        const float* __restrict__ be)
{
    __shared__ float r1[256], r2[256];
    int tid = threadIdx.x, j = tid & 63, part = tid >> 6;
    float s = 0.f, s2 = 0.f;
    for (int b = part; b < 128; b += 4) { s += g_part[b * 64 + j]; s2 += g_part2[b * 64 + j]; }
    r1[tid] = s; r2[tid] = s2;
    __syncthreads();
    if (tid < 64) {
        for (int p = 1; p < 4; p++) { s += r1[tid + 64 * p]; s2 += r2[tid + 64 * p]; }
        float m = s * (1.f / 2048.f);
        float v = s2 * (1.f / 2048.f) - m * m;
        float sc = g[tid] * rsqrtf(v + 1e-5f);
        g_sc1[tid] = sc;
        g_sh1[tid] = be[tid] - m * sc;
    }
}

// ---------------------------------------------------------------------------
// K4: prep = LSTM2 single step from zero state (blocks 0..127) + base vectors
// (blocks 128..142).  block 128 threads.
// ---------------------------------------------------------------------------
__global__ void __launch_bounds__(128) prep_kernel(
    const float* __restrict__ ops, const float* __restrict__ ext,
    const float* __restrict__ card, const float* __restrict__ Wih2,
    const float* __restrict__ b2, const float* __restrict__ Win,
    const float* __restrict__ bin_)
{
    __shared__ float x[88];
    int b = blockIdx.x, k = threadIdx.x;
    int row = (b < 128) ? (15 * 128 + b) : ((b - 128) * 128 + 0);
    if (k < 15)      x[k] = ops[row * 15 + k];
    else if (k < 22) x[k] = ext[row * 7 + (k - 15)];
    else if (k < 24) x[k] = card[row * 2 + (k - 22)];
    else if (k < 88) x[k] = g_lo[(size_t)row * 64 + (k - 24)] * g_sc1[k - 24] + g_sh1[k - 24];
    __syncthreads();

    if (b < 128) {
        float gi = b2[k], gg = b2[256 + k], go = b2[384 + k];
        for (int j = 0; j < 88; j++) {
            float xv = x[j];
            const float* w = Wih2 + j * 512;
            gi += xv * w[k];
            gg += xv * w[256 + k];
            go += xv * w[384 + k];
        }
        float c = sigf(gi) * tanh_(gg);  // sig(f)*c_prev = 0
        float h = sigf(go) * tanh_(c);
        g_h[0][b * 128 + k] = h;
        g_c[0][b * 128 + k] = c;
    } else {
        int l = b - 128;
        float s = bin_[k];
        for (int j = 0; j < 88; j++) s += x[j] * Win[j * 128 + k];
        g_base[(14 - l) * 128 + k] = s;
    }
}

// ---------------------------------------------------------------------------
// K5: fused tree scan — all 15 steps in one persistent kernel.
// grid (8,5) = 40 blocks, block 256 (k split across warp halves).
// ---------------------------------------------------------------------------
__global__ void __launch_bounds__(256) tree_kernel(const int* __restrict__ mapping)
{
    const unsigned int NB = 40;
    __shared__ float A[16][257];
    __shared__ float red[16 * 128];
    int tid = threadIdx.x, bx = blockIdx.x, g = blockIdx.y;
    int bid = blockIdx.y * 8 + blockIdx.x;

    for (int s = 0; s < 15; s++) {
        int lvl = 14 - s, p = s & 1;
        const float* __restrict__ hprev = g_h[p];

        // gather A = [lh|rh] rows for this block's 16 n
        for (int i = tid; i < 16 * 256; i += 256) {
            int r = i >> 8, h = i & 255;
            int n = bx * 16 + r;
            int mp = mapping[(lvl * 128 + n) * 2 + (h >> 7)];
            A[r][h] = (mp > 0) ? hprev[(mp - 1) * 128 + (h & 127)] : 0.f;
        }
        __syncthreads();

        // GEMM 16x128 tile for gate g, k split: half 0 -> k 0..127, half 1 -> 128..255
        int half = tid >> 7, t128 = tid & 127;
        int trp = t128 >> 4, tc = t128 & 15;
        int r0 = trp * 2;
        unsigned long long a00 = 0, a01 = 0, a02 = 0, a03 = 0;
        unsigned long long a10 = 0, a11 = 0, a12 = 0, a13 = 0;
        const float* W = g_Wcat + g * 128 + tc * 8;
        int k0 = half * 128;
#pragma unroll 4
        for (int kk = 0; kk < 128; kk++) {
            int k = k0 + kk;
            unsigned long long v0 = dup2(A[r0][k]);
            unsigned long long v1 = dup2(A[r0 + 1][k]);
            const ulonglong2* wp = (const ulonglong2*)(W + (size_t)k * 640);
            ulonglong2 w0 = wp[0], w1 = wp[1];
            fma2(a00, v0, w0.x); fma2(a01, v0, w0.y); fma2(a02, v0, w1.x); fma2(a03, v0, w1.y);
            fma2(a10, v1, w0.x); fma2(a11, v1, w0.y); fma2(a12, v1, w1.x); fma2(a13, v1, w1.y);
        }
        if (half == 1) {
            ulonglong2* R0 = (ulonglong2*)(red + r0 * 128 + tc * 8);
            ulonglong2* R1 = (ulonglong2*)(red + (r0 + 1) * 128 + tc * 8);
            R0[0] = make_ulonglong2(a00, a01); R0[1] = make_ulonglong2(a02, a03);
            R1[0] = make_ulonglong2(a10, a11); R1[1] = make_ulonglong2(a12, a13);
        }
        __syncthreads();
        if (half == 0) {
            const ulonglong2* R0 = (const ulonglong2*)(red + r0 * 128 + tc * 8);
            const ulonglong2* R1 = (const ulonglong2*)(red + (r0 + 1) * 128 + tc * 8);
            ulonglong2 q0 = R0[0], q1 = R0[1], q2 = R1[0], q3 = R1[1];
            add2(a00, q0.x); add2(a01, q0.y); add2(a02, q1.x); add2(a03, q1.y);
            add2(a10, q2.x); add2(a11, q2.y); add2(a12, q3.x); add2(a13, q3.y);
            int n0 = bx * 16 + r0;
            ulonglong2* P0 = (ulonglong2*)(g_P + (size_t)n0 * 640 + g * 128 + tc * 8);
            ulonglong2* P1 = (ulonglong2*)(g_P + (size_t)(n0 + 1) * 640 + g * 128 + tc * 8);
            P0[0] = make_ulonglong2(a00, a01); P0[1] = make_ulonglong2(a02, a03);
            P1[0] = make_ulonglong2(a10, a11); P1[1] = make_ulonglong2(a12, a13);
        }

        grid_barrier(NB);

        // pointwise cell update over 128x128 elems, spread on 10240 threads
        for (int idx = bid * 256 + tid; idx < 16384; idx += 10240) {
            int n = idx >> 7, k = idx & 127;
            int mp0 = mapping[(lvl * 128 + n) * 2 + 0];
            int mp1 = mapping[(lvl * 128 + n) * 2 + 1];
            float lc = (mp0 > 0) ? g_c[p][(mp0 - 1) * 128 + k] : 0.f;
            float rc = (mp1 > 0) ? g_c[p][(mp1 - 1) * 128 + k] : 0.f;
            float bse = g_base[s * 128 + k];
            const float* P = g_P + (size_t)n * 640;
            float pre[5];
#pragma unroll
            for (int q = 0; q < 5; q++)
                pre[q] = bse + P[q * 128 + k] + g_bb[q * 128 + k];
            float i = sigf(pre[0]), lf = sigf(pre[1]), rf = sigf(pre[2]);
            float u = tanh_(pre[3]), o = sigf(pre[4]);
            float c = i * u + lf * lc + rf * rc;
            g_c[1 - p][n * 128 + k] = c;
            g_h[1 - p][n * 128 + k] = o * tanh_(c);
        }

        grid_barrier(NB);
    }
}

// ---------------------------------------------------------------------------
// K6: fused tail: BN2 -> t1 -> BN3 -> t2 -> sigmoid output.  One block, 256.
// ---------------------------------------------------------------------------
__global__ void __launch_bounds__(256) tail_kernel(
    const float* __restrict__ g2, const float* __restrict__ be2,
    const float* __restrict__ Wt1, const float* __restrict__ bt1,
    const float* __restrict__ g3, const float* __restrict__ be3,
    const float* __restrict__ Wt2, const float* __restrict__ bt2,
    const float* __restrict__ Wo, const float* __restrict__ bo,
    float* __restrict__ out)
{
    __shared__ float t1s[128 * 64];  // 32KB
    __shared__ float sc[128], sh[128];
    __shared__ float red[256], red2[256];
    int tid = threadIdx.x;

    // BN2 stats over g_h[1] (128x128)
    {
        int col = tid & 127, part = tid >> 7;
        float s = 0.f, s2 = 0.f;
        for (int r = part; r < 128; r += 2) {
            float v = g_h[1][r * 128 + col];
            s += v; s2 += v * v;
        }
        red[tid] = s; red2[tid] = s2;
        __syncthreads();
        if (tid < 128) {
            s = red[tid] + red[tid + 128];
            s2 = red2[tid] + red2[tid + 128];
            float m = s * (1.f / 128.f);
            float v = s2 * (1.f / 128.f) - m * m;
            float scl = g2[tid] * rsqrtf(v + 1e-5f);
            sc[tid] = scl;
            sh[tid] = be2[tid] - m * scl;
        }
        __syncthreads();
    }

    // t1 = relu(bn2(h) @ Wt1 + bt1)  (128x64)
    for (int o = tid; o < 8192; o += 256) {
        int n = o >> 6, j = o & 63;
        float acc = bt1[j];
        for (int h = 0; h < 128; h++)
            acc += (g_h[1][n * 128 + h] * sc[h] + sh[h]) * Wt1[h * 64 + j];
        t1s[o] = fmaxf(acc, 0.f);
    }
    __syncthreads();

    // BN3 stats over t1s (128x64)
    {
        int col = tid & 63, part = tid >> 6;
        float s = 0.f, s2 = 0.f;
        for (int r = part; r < 128; r += 4) {
            float v = t1s[r * 64 + col];
            s += v; s2 += v * v;
        }
        red[tid] = s; red2[tid] = s2;
        __syncthreads();
        if (tid < 64) {
            for (int p = 1; p < 4; p++) { s += red[tid + 64 * p]; s2 += red2[tid + 64 * p]; }
            float m = s * (1.f / 128.f);
            float v = s2 * (1.f / 128.f) - m * m;
            float scl = g3[tid] * rsqrtf(v + 1e-5f);
            sc[tid] = scl;
            sh[tid] = be3[tid] - m * scl;
        }
        __syncthreads();
    }

    // t2 = relu(bn3(t1)@Wt2+bt2); out = sigmoid(t2@Wo+bo)
    if (tid < 128) {
        int n = tid;
        float tn[64];
#pragma unroll
        for (int i = 0; i < 64; i++) tn[i] = t1s[n * 64 + i] * sc[i] + sh[i];
        float a = bo[0];
        for (int j = 0; j < 64; j++) {
            float s = bt2[j];
#pragma unroll
            for (int i = 0; i < 64; i++) s += tn[i] * Wt2[i * 64 + j];
            a += fmaxf(s, 0.f) * Wo[j];
        }
        out[n] = sigf(a);
    }
}

// ---------------------------------------------------------------------------
extern "C" void kernel_launch(void* const* d_in, const int* in_sizes, int n_in,
                              void* d_out, int out_size)
{
    const float* operators = (const float*)d_in[0];
    const float* extra     = (const float*)d_in[1];
    const float* card      = (const float*)d_in[2];
    const float* cond1     = (const float*)d_in[3];
    const float* cond2     = (const float*)d_in[4];
    const int*   mapping   = (const int*)  d_in[5];
    const float* Wih1      = (const float*)d_in[6];
    const float* Whh1      = (const float*)d_in[7];
    const float* b1        = (const float*)d_in[8];
    const float* Wc        = (const float*)d_in[9];
    const float* bc        = (const float*)d_in[10];
    const float* g1        = (const float*)d_in[11];
    const float* be1       = (const float*)d_in[12];
    const float* Wih2      = (const float*)d_in[13];
    // d_in[14] = Whh2: unused (single step from zero state)
    const float* b2        = (const float*)d_in[15];
    const float* Win       = (const float*)d_in[16];
    const float* bin_      = (const float*)d_in[17];
    const float* Wlh       = (const float*)d_in[18];
    const float* blh       = (const float*)d_in[19];
    const float* Wrh       = (const float*)d_in[20];
    const float* brh       = (const float*)d_in[21];
    const float* g2        = (const float*)d_in[22];
    const float* be2       = (const float*)d_in[23];
    const float* Wt1       = (const float*)d_in[24];
    const float* bt1       = (const float*)d_in[25];
    const float* g3        = (const float*)d_in[26];
    const float* be3       = (const float*)d_in[27];
    const float* Wt2       = (const float*)d_in[28];
    const float* bt2       = (const float*)d_in[29];
    const float* Wo        = (const float*)d_in[30];
    const float* bo        = (const float*)d_in[31];
    float* out = (float*)d_out;

    const int LSTM1_SMEM = 110592;
    cudaFuncSetAttribute(lstm1_kernel,
                         cudaFuncAttributeMaxDynamicSharedMemorySize, LSTM1_SMEM);

    // ordering: lstm1 at our idx 3 so ncu (-s 5) profiles it.
    wcat_kernel<<<160, 1024>>>(Wlh, Wrh);
    bb_kernel<<<1, 640>>>(blh, brh);
    b1copy_kernel<<<1, 512>>>(b1);
    lstm1_kernel<<<128, 256, LSTM1_SMEM>>>(cond1, cond2, Wih1, Whh1);
    lo_kernel<<<128, 256>>>(Wc, bc);
    bn1_final_kernel<<<1, 256>>>(g1, be1);
    prep_kernel<<<143, 128>>>(operators, extra, card, Wih2, b2, Win, bin_);
    tree_kernel<<<dim3(8, 5), 256>>>(mapping);
    tail_kernel<<<1, 256>>>(g2, be2, Wt1, bt1, g3, be3, Wt2, bt2, Wo, bo, out);
}

// round 7
// speedup vs baseline: 2.2611x; 1.3722x over previous
#include <cuda_runtime.h>
#include <cstdint>

// Shapes: L=16, N=128, C=10, D=13, H=128, HID=64, F=88
#define DINL __device__ __forceinline__

// ------------------------- device scratch -------------------------
__device__ __align__(16) float g_h1[4096 * 128];   // LSTM1 final hidden
__device__ __align__(16) float g_lo[2048 * 64];    // lo pre-BN
__device__ __align__(16) float g_part[128 * 64];   // BN1 partial sums
__device__ __align__(16) float g_part2[128 * 64];  // BN1 partial sumsq
__device__ float g_sc1[64], g_sh1[64];             // BN1 scale/shift
__device__ __align__(16) float g_Wcat[256 * 640];  // [Wlh|Wrh] repacked
__device__ __align__(16) float g_bb[5 * 128];      // blh+brh combined
__device__ __align__(16) float g_b1c[512];         // b1 copy
__device__ float g_base[15 * 128];                 // per-step base vectors (a=0)
__device__ __align__(16) float g_h[2][128 * 128];  // tree h state (ping-pong)
__device__ __align__(16) float g_c[2][128 * 128];  // tree c state (ping-pong)
__device__ __align__(16) float g_P[128 * 640];     // tree projection per step
__device__ unsigned int g_bar_count;               // grid barrier (zero-init)
__device__ unsigned int g_bar_gen;

// ------------------------- helpers -------------------------
DINL float sigf(float x) { return __fdividef(1.f, 1.f + __expf(-x)); }
DINL float tanh_(float x) { return 2.f * sigf(2.f * x) - 1.f; }
DINL void fma2(unsigned long long& a, unsigned long long b, unsigned long long c) {
    asm("fma.rn.f32x2 %0, %1, %2, %0;" : "+l"(a) : "l"(b), "l"(c));
}
DINL void add2(unsigned long long& a, unsigned long long b) {
    asm("add.rn.f32x2 %0, %0, %1;" : "+l"(a) : "l"(b));
}
DINL unsigned long long dup2(float x) {
    unsigned long long r;
    asm("mov.b64 %0, {%1, %1};" : "=l"(r) : "f"(x));
    return r;
}
DINL float2 unp2(unsigned long long v) {
    float2 f;
    asm("mov.b64 {%0, %1}, %2;" : "=f"(f.x), "=f"(f.y) : "l"(v));
    return f;
}
DINL void cpasync16(uint32_t dst, const void* src) {
    asm volatile("cp.async.ca.shared.global [%0], [%1], 16;" :: "r"(dst), "l"(src) : "memory");
}
DINL void cp_commit() { asm volatile("cp.async.commit_group;" ::: "memory"); }
DINL void cp_wait1() { asm volatile("cp.async.wait_group 1;" ::: "memory"); }
DINL void cp_wait0() { asm volatile("cp.async.wait_group 0;" ::: "memory"); }

// Software grid barrier (sense via generation counter). 40 co-resident blocks.
DINL void grid_barrier(unsigned int nb) {
    __syncthreads();
    if (threadIdx.x == 0) {
        __threadfence();
        unsigned int gen = *(volatile unsigned int*)&g_bar_gen;
        if (atomicAdd(&g_bar_count, 1u) == nb - 1) {
            atomicExch(&g_bar_count, 0u);
            __threadfence();
            atomicExch(&g_bar_gen, gen + 1u);
        } else {
            while (*(volatile unsigned int*)&g_bar_gen == gen) {}
        }
        __threadfence();
    }
    __syncthreads();
}

// ---------------------------------------------------------------------------
// P1: repack Wcat[h, g*128+k] = h<128 ? Wlh[g,h,k] : Wrh[g,h-128,k]
// ---------------------------------------------------------------------------
__global__ void __launch_bounds__(1024) wcat_kernel(const float* __restrict__ Wlh,
                                                    const float* __restrict__ Wrh)
{
    int i = blockIdx.x * 1024 + threadIdx.x;
    if (i >= 256 * 640) return;
    int h = i / 640, col = i - h * 640;
    int g = col >> 7, k = col & 127;
    g_Wcat[i] = (h < 128) ? Wlh[g * 16384 + h * 128 + k]
                          : Wrh[g * 16384 + (h - 128) * 128 + k];
}

// P2: combined tree bias
__global__ void __launch_bounds__(640) bb_kernel(const float* __restrict__ blh,
                                                 const float* __restrict__ brh)
{
    int i = threadIdx.x;
    g_bb[i] = blh[i] + brh[i];
}

// P3: b1 copy + barrier reset
__global__ void __launch_bounds__(512) b1copy_kernel(const float* __restrict__ b1)
{
    int i = threadIdx.x;
    g_b1c[i] = b1[i];
    if (i == 0) { g_bar_count = 0u; }
}

// ---------------------------------------------------------------------------
// K1: LSTM1, gate-split: block 256 = 8 warps.  Warp w: gate pair gp = w>>2
// (gp0 -> gates i,f; gp1 -> gates g,o), rows lr0 = (w&3)*8 .. +8.
// Weights staged via cp.async double-buffered 16-k tiles; Wih resident.
// smem (floats): z[32][144] 4608 | wihs 6656 | ws 16384 | gb[32][264] 8448
// total 36096 floats = 144384 B.
// ---------------------------------------------------------------------------
DINL void stage_tile(uint32_t ws_addr, const float* Whh, int tile, int buf, int tid) {
    const char* src = (const char*)(Whh + tile * 8192) + tid * 16;
    uint32_t dst = ws_addr + buf * 32768 + tid * 16;
#pragma unroll
    for (int i = 0; i < 8; i++)
        cpasync16(dst + i * 4096, src + i * 4096);
}

__global__ void __launch_bounds__(256) lstm1_kernel(
    const float* __restrict__ cond1, const float* __restrict__ cond2,
    const float* __restrict__ Wih, const float* __restrict__ Whh)
{
    extern __shared__ float smem[];
    float (*z)[144] = (float (*)[144])smem;
    float* wihs = smem + 4608;
    float* ws   = smem + 4608 + 6656;
    float (*gb)[264] = (float (*)[264])(smem + 4608 + 6656 + 16384);
    uint32_t wih_addr = (uint32_t)__cvta_generic_to_shared(wihs);
    uint32_t ws_addr  = (uint32_t)__cvta_generic_to_shared(ws);

    const int tid = threadIdx.x, warp = tid >> 5, lane = tid & 31;
    const int gp = warp >> 2;            // gate pair: 0 -> (i,f), 1 -> (g,o)
    const int lr0 = (warp & 3) * 8;      // 8 rows per warp
    const int brow0 = blockIdx.x * 32;

    // stage Wih once (1664 x 16B)
    for (int i = tid; i < 1664; i += 256)
        cpasync16(wih_addr + i * 16, (const char*)Wih + i * 16);
    cp_commit();
    // prefetch Whh tile 0
    stage_tile(ws_addr, Whh, 0, 0, tid);
    cp_commit();

    // zero h region of z
    for (int i = tid; i < 4096; i += 256) z[i >> 7][i & 127] = 0.f;

    float cst[8][4] = {};
    const float* src[8];
#pragma unroll
    for (int r = 0; r < 8; r++) {
        int gr = brow0 + lr0 + r;
        src[r] = (gr < 2048) ? (cond1 + (size_t)gr * 130)
                             : (cond2 + (size_t)(gr - 2048) * 130);
    }

    unsigned long long bias[4];
    {
        ulonglong2 ba = *(const ulonglong2*)(g_b1c + (gp * 2) * 128 + lane * 4);
        ulonglong2 bbv = *(const ulonglong2*)(g_b1c + (gp * 2 + 1) * 128 + lane * 4);
        bias[0] = ba.x; bias[1] = ba.y; bias[2] = bbv.x; bias[3] = bbv.y;
    }

    for (int t = 0; t < 10; t++) {
        if (gp == 0) {
            for (int idx = lane; idx < 104; idx += 32) {
                int r = idx / 13, c = idx - r * 13;
                z[lr0 + r][128 + c] = src[r][t * 13 + c];
            }
        }
        __syncthreads();

        unsigned long long acc[8][4];
#pragma unroll
        for (int r = 0; r < 8; r++)
#pragma unroll
            for (int j = 0; j < 4; j++) acc[r][j] = bias[j];

        // h @ Whh via pipelined smem tiles (8 tiles of 16 k)
        for (int kt = 0; kt < 8; kt++) {
            stage_tile(ws_addr, Whh, (kt + 1) & 7, (kt + 1) & 1, tid);
            cp_commit();
            cp_wait1();
            __syncthreads();
            const ulonglong2* W = (const ulonglong2*)(ws + (kt & 1) * 8192);
#pragma unroll
            for (int kk4 = 0; kk4 < 4; kk4++) {
                float4 a4[8];
#pragma unroll
                for (int r = 0; r < 8; r++)
                    a4[r] = *(const float4*)&z[lr0 + r][kt * 16 + kk4 * 4];
#pragma unroll
                for (int q = 0; q < 4; q++) {
                    int kk = kk4 * 4 + q;
                    ulonglong2 w0 = W[kk * 128 + gp * 64 + lane];
                    ulonglong2 w1 = W[kk * 128 + gp * 64 + 32 + lane];
#pragma unroll
                    for (int r = 0; r < 8; r++) {
                        float zv = (q == 0) ? a4[r].x : (q == 1) ? a4[r].y
                                 : (q == 2) ? a4[r].z : a4[r].w;
                        unsigned long long a = dup2(zv);
                        fma2(acc[r][0], a, w0.x); fma2(acc[r][1], a, w0.y);
                        fma2(acc[r][2], a, w1.x); fma2(acc[r][3], a, w1.y);
                    }
                }
            }
            __syncthreads();
        }

        // x @ Wih from resident smem
        {
            const ulonglong2* Wx = (const ulonglong2*)wihs;
#pragma unroll 4
            for (int k = 0; k < 13; k++) {
                ulonglong2 w0 = Wx[k * 128 + gp * 64 + lane];
                ulonglong2 w1 = Wx[k * 128 + gp * 64 + 32 + lane];
#pragma unroll
                for (int r = 0; r < 8; r++) {
                    unsigned long long a = dup2(z[lr0 + r][128 + k]);
                    fma2(acc[r][0], a, w0.x); fma2(acc[r][1], a, w0.y);
                    fma2(acc[r][2], a, w1.x); fma2(acc[r][3], a, w1.y);
                }
            }
        }

        // exchange: gp1 warps publish (g,o) pre-activations
        if (gp == 1) {
#pragma unroll
            for (int r = 0; r < 8; r++) {
                *(ulonglong2*)&gb[lr0 + r][lane * 4] =
                    make_ulonglong2(acc[r][0], acc[r][1]);          // g gate
                *(ulonglong2*)&gb[lr0 + r][132 + lane * 4] =
                    make_ulonglong2(acc[r][2], acc[r][3]);          // o gate
            }
        }
        __syncthreads();

        if (gp == 0) {
#pragma unroll
            for (int r = 0; r < 8; r++) {
                ulonglong2 ggu = *(const ulonglong2*)&gb[lr0 + r][lane * 4];
                ulonglong2 gou = *(const ulonglong2*)&gb[lr0 + r][132 + lane * 4];
                float2 i01 = unp2(acc[r][0]), i23 = unp2(acc[r][1]);
                float2 f01 = unp2(acc[r][2]), f23 = unp2(acc[r][3]);
                float2 G01 = unp2(ggu.x), G23 = unp2(ggu.y);
                float2 o01 = unp2(gou.x), o23 = unp2(gou.y);
                float iv[4] = {i01.x, i01.y, i23.x, i23.y};
                float fv[4] = {f01.x, f01.y, f23.x, f23.y};
                float gv[4] = {G01.x, G01.y, G23.x, G23.y};
                float ov[4] = {o01.x, o01.y, o23.x, o23.y};
                float hv[4];
#pragma unroll
                for (int q = 0; q < 4; q++) {
                    float c = sigf(fv[q]) * cst[r][q] + sigf(iv[q]) * tanh_(gv[q]);
                    cst[r][q] = c;
                    hv[q] = sigf(ov[q]) * tanh_(c);
                }
                *(float4*)&z[lr0 + r][lane * 4] = make_float4(hv[0], hv[1], hv[2], hv[3]);
            }
        }
        // next-iteration __syncthreads makes h visible to all warps
    }
    __syncthreads();

    for (int i = tid; i < 4096; i += 256)
        g_h1[(size_t)(brow0 + (i >> 7)) * 128 + (i & 127)] = z[i >> 7][i & 127];
}

// ---------------------------------------------------------------------------
// K2: lo = 0.5*(relu(h1@Wc+bc)+relu(h2@Wc+bc)) (2048x64), 16 rows/block,
// plus deterministic per-block BN1 partial sums.
// ---------------------------------------------------------------------------
__global__ void __launch_bounds__(256) lo_kernel(const float* __restrict__ Wc,
                                                 const float* __restrict__ bc)
{
    __shared__ float ha[16][128], hb[16][128];
    __shared__ float red[256], red2[256];
    int tid = threadIdx.x, r0 = blockIdx.x * 16;
    for (int i = tid; i < 16 * 128; i += 256) {
        int r = i >> 7, h = i & 127;
        ha[r][h] = g_h1[(size_t)(r0 + r) * 128 + h];
        hb[r][h] = g_h1[(size_t)(2048 + r0 + r) * 128 + h];
    }
    __syncthreads();
    int j = tid & 63;
    float ps = 0.f, ps2 = 0.f;
#pragma unroll
    for (int rg = 0; rg < 4; rg++) {
        int r = (tid >> 6) + rg * 4;
        float s1 = bc[j], s2 = s1;
        for (int h = 0; h < 128; h++) {
            float w = Wc[h * 64 + j];
            s1 += ha[r][h] * w;
            s2 += hb[r][h] * w;
        }
        float v = 0.5f * (fmaxf(s1, 0.f) + fmaxf(s2, 0.f));
        g_lo[(size_t)(r0 + r) * 64 + j] = v;
        ps += v; ps2 += v * v;
    }
    red[tid] = ps; red2[tid] = ps2;
    __syncthreads();
    if (tid < 64) {
        for (int p = 1; p < 4; p++) { ps += red[tid + 64 * p]; ps2 += red2[tid + 64 * p]; }
        g_part[blockIdx.x * 64 + tid] = ps;
        g_part2[blockIdx.x * 64 + tid] = ps2;
    }
}

// K2b: finalize BN1 stats -> scale/shift
__global__ void __launch_bounds__(256) bn1_final_kernel(const float* __restrict__ g,
                                                        const float* __restrict__ be)
{
    __shared__ float r1[256], r2[256];
    int tid = threadIdx.x, j = tid & 63, part = tid >> 6;
    float s = 0.f, s2 = 0.f;
    for (int b = part; b < 128; b += 4) { s += g_part[b * 64 + j]; s2 += g_part2[b * 64 + j]; }
    r1[tid] = s; r2[tid] = s2;
    __syncthreads();
    if (tid < 64) {
        for (int p = 1; p < 4; p++) { s += r1[tid + 64 * p]; s2 += r2[tid + 64 * p]; }
        float m = s * (1.f / 2048.f);
        float v = s2 * (1.f / 2048.f) - m * m;
        float sc = g[tid] * rsqrtf(v + 1e-5f);
        g_sc1[tid] = sc;
        g_sh1[tid] = be[tid] - m * sc;
    }
}

// ---------------------------------------------------------------------------
// K4: prep = LSTM2 single step from zero state (blocks 0..127) + base vectors
// (blocks 128..142).  block 128 threads.
// ---------------------------------------------------------------------------
__global__ void __launch_bounds__(128) prep_kernel(
    const float* __restrict__ ops, const float* __restrict__ ext,
    const float* __restrict__ card, const float* __restrict__ Wih2,
    const float* __restrict__ b2, const float* __restrict__ Win,
    const float* __restrict__ bin_)
{
    __shared__ float x[88];
    int b = blockIdx.x, k = threadIdx.x;
    int row = (b < 128) ? (15 * 128 + b) : ((b - 128) * 128 + 0);
    if (k < 15)      x[k] = ops[row * 15 + k];
    else if (k < 22) x[k] = ext[row * 7 + (k - 15)];
    else if (k < 24) x[k] = card[row * 2 + (k - 22)];
    else if (k < 88) x[k] = g_lo[(size_t)row * 64 + (k - 24)] * g_sc1[k - 24] + g_sh1[k - 24];
    __syncthreads();

    if (b < 128) {
        float gi = b2[k], gg = b2[256 + k], go = b2[384 + k];
        for (int j = 0; j < 88; j++) {
            float xv = x[j];
            const float* w = Wih2 + j * 512;
            gi += xv * w[k];
            gg += xv * w[256 + k];
            go += xv * w[384 + k];
        }
        float c = sigf(gi) * tanh_(gg);  // sig(f)*c_prev = 0
        float h = sigf(go) * tanh_(c);
        g_h[0][b * 128 + k] = h;
        g_c[0][b * 128 + k] = c;
    } else {
        int l = b - 128;
        float s = bin_[k];
        for (int j = 0; j < 88; j++) s += x[j] * Win[j * 128 + k];
        g_base[(14 - l) * 128 + k] = s;
    }
}

// ---------------------------------------------------------------------------
// K5: fused tree scan — all 15 steps in one persistent kernel.
// grid (8,5) = 40 blocks, block 256.  Entire 256x128 W slice for this block's
// gate is staged ONCE into smem (128KB) via cp.async; all 15 steps read smem.
// Thread layout: half = tid>>7 (k range 128*half), warp4 = (tid>>5)&3 ->
// rows r0 = bx*16 + warp4*4, lane -> cols lane*4.  4 rows x 4 cols per thread.
// smem (floats): Wsm 32768 | A[16][264] 4224 | red 2048 -> 39040 f = 156160 B.
// ---------------------------------------------------------------------------
__global__ void __launch_bounds__(256) tree_kernel(const int* __restrict__ mapping)
{
    const unsigned int NB = 40;
    extern __shared__ float smem[];
    float* Wsm = smem;
    float (*A)[264] = (float (*)[264])(smem + 32768);
    float* red = smem + 32768 + 4224;
    uint32_t wsm_addr = (uint32_t)__cvta_generic_to_shared(Wsm);

    int tid = threadIdx.x, bx = blockIdx.x, g = blockIdx.y;
    int bid = g * 8 + bx;

    // stage W slice: Wsm[k][c] = g_Wcat[k*640 + g*128 + c], k 0..255, c 0..127
    // each row = 128 floats = 32 x 16B chunks  (FIX: was i>>3 / i&7 — OOB)
    for (int i = tid; i < 8192; i += 256)
        cpasync16(wsm_addr + i * 16,
                  g_Wcat + (size_t)(i >> 5) * 640 + g * 128 + (i & 31) * 4);
    cp_commit();
    cp_wait0();
    __syncthreads();

    const int half = tid >> 7, t128 = tid & 127;
    const int warp4 = t128 >> 5, lane = t128 & 31;
    const int r0 = warp4 * 4;
    const int k0 = half * 128;
    const ulonglong2* Wu2 = (const ulonglong2*)Wsm;

    for (int s = 0; s < 15; s++) {
        int lvl = 14 - s, p = s & 1;
        const float* __restrict__ hprev = g_h[p];

        // gather A = [lh|rh] rows for this block's 16 n
        for (int i = tid; i < 16 * 256; i += 256) {
            int r = i >> 8, h = i & 255;
            int n = bx * 16 + r;
            int mp = mapping[(lvl * 128 + n) * 2 + (h >> 7)];
            A[r][h] = (mp > 0) ? hprev[(mp - 1) * 128 + (h & 127)] : 0.f;
        }
        __syncthreads();

        unsigned long long acc[8];
#pragma unroll
        for (int j = 0; j < 8; j++) acc[j] = 0ull;

#pragma unroll 2
        for (int kk4 = 0; kk4 < 32; kk4++) {
            float4 a4[4];
#pragma unroll
            for (int r = 0; r < 4; r++)
                a4[r] = *(const float4*)&A[r0 + r][k0 + kk4 * 4];
#pragma unroll
            for (int q = 0; q < 4; q++) {
                int k = k0 + kk4 * 4 + q;
                ulonglong2 w = Wu2[k * 32 + lane];
#pragma unroll
                for (int r = 0; r < 4; r++) {
                    float av = (q == 0) ? a4[r].x : (q == 1) ? a4[r].y
                             : (q == 2) ? a4[r].z : a4[r].w;
                    unsigned long long v = dup2(av);
                    fma2(acc[r * 2], v, w.x);
                    fma2(acc[r * 2 + 1], v, w.y);
                }
            }
        }

        if (half == 1) {
#pragma unroll
            for (int r = 0; r < 4; r++)
                *(ulonglong2*)&red[(r0 + r) * 128 + lane * 4] =
                    make_ulonglong2(acc[r * 2], acc[r * 2 + 1]);
        }
        __syncthreads();
        if (half == 0) {
#pragma unroll
            for (int r = 0; r < 4; r++) {
                ulonglong2 q2 = *(const ulonglong2*)&red[(r0 + r) * 128 + lane * 4];
                add2(acc[r * 2], q2.x);
                add2(acc[r * 2 + 1], q2.y);
                *(ulonglong2*)(g_P + (size_t)(bx * 16 + r0 + r) * 640 + g * 128 + lane * 4) =
                    make_ulonglong2(acc[r * 2], acc[r * 2 + 1]);
            }
        }

        grid_barrier(NB);

        // pointwise cell update over 128x128 elems, spread on 10240 threads
        for (int idx = bid * 256 + tid; idx < 16384; idx += 10240) {
            int n = idx >> 7, k = idx & 127;
            int mp0 = mapping[(lvl * 128 + n) * 2 + 0];
            int mp1 = mapping[(lvl * 128 + n) * 2 + 1];
            float lc = (mp0 > 0) ? g_c[p][(mp0 - 1) * 128 + k] : 0.f;
            float rc = (mp1 > 0) ? g_c[p][(mp1 - 1) * 128 + k] : 0.f;
            float bse = g_base[s * 128 + k];
            const float* P = g_P + (size_t)n * 640;
            float pre[5];
#pragma unroll
            for (int q = 0; q < 5; q++)
                pre[q] = bse + P[q * 128 + k] + g_bb[q * 128 + k];
            float i = sigf(pre[0]), lf = sigf(pre[1]), rf = sigf(pre[2]);
            float u = tanh_(pre[3]), o = sigf(pre[4]);
            float c = i * u + lf * lc + rf * rc;
            g_c[1 - p][n * 128 + k] = c;
            g_h[1 - p][n * 128 + k] = o * tanh_(c);
        }

        grid_barrier(NB);
    }
}

// ---------------------------------------------------------------------------
// K6: fused tail: BN2 -> t1 -> BN3 -> t2 -> sigmoid output.  One block, 256.
// ---------------------------------------------------------------------------
__global__ void __launch_bounds__(256) tail_kernel(
    const float* __restrict__ g2, const float* __restrict__ be2,
    const float* __restrict__ Wt1, const float* __restrict__ bt1,
    const float* __restrict__ g3, const float* __restrict__ be3,
    const float* __restrict__ Wt2, const float* __restrict__ bt2,
    const float* __restrict__ Wo, const float* __restrict__ bo,
    float* __restrict__ out)
{
    __shared__ float t1s[128 * 64];  // 32KB
    __shared__ float sc[128], sh[128];
    __shared__ float red[256], red2[256];
    int tid = threadIdx.x;

    // BN2 stats over g_h[1] (128x128)
    {
        int col = tid & 127, part = tid >> 7;
        float s = 0.f, s2 = 0.f;
        for (int r = part; r < 128; r += 2) {
            float v = g_h[1][r * 128 + col];
            s += v; s2 += v * v;
        }
        red[tid] = s; red2[tid] = s2;
        __syncthreads();
        if (tid < 128) {
            s = red[tid] + red[tid + 128];
            s2 = red2[tid] + red2[tid + 128];
            float m = s * (1.f / 128.f);
            float v = s2 * (1.f / 128.f) - m * m;
            float scl = g2[tid] * rsqrtf(v + 1e-5f);
            sc[tid] = scl;
            sh[tid] = be2[tid] - m * scl;
        }
        __syncthreads();
    }

    // t1 = relu(bn2(h) @ Wt1 + bt1)  (128x64)
    for (int o = tid; o < 8192; o += 256) {
        int n = o >> 6, j = o & 63;
        float acc = bt1[j];
        for (int h = 0; h < 128; h++)
            acc += (g_h[1][n * 128 + h] * sc[h] + sh[h]) * Wt1[h * 64 + j];
        t1s[o] = fmaxf(acc, 0.f);
    }
    __syncthreads();

    // BN3 stats over t1s (128x64)
    {
        int col = tid & 63, part = tid >> 6;
        float s = 0.f, s2 = 0.f;
        for (int r = part; r < 128; r += 4) {
            float v = t1s[r * 64 + col];
            s += v; s2 += v * v;
        }
        red[tid] = s; red2[tid] = s2;
        __syncthreads();
        if (tid < 64) {
            for (int p = 1; p < 4; p++) { s += red[tid + 64 * p]; s2 += red2[tid + 64 * p]; }
            float m = s * (1.f / 128.f);
            float v = s2 * (1.f / 128.f) - m * m;
            float scl = g3[tid] * rsqrtf(v + 1e-5f);
            sc[tid] = scl;
            sh[tid] = be3[tid] - m * scl;
        }
        __syncthreads();
    }

    // t2 = relu(bn3(t1)@Wt2+bt2); out = sigmoid(t2@Wo+bo)
    if (tid < 128) {
        int n = tid;
        float tn[64];
#pragma unroll
        for (int i = 0; i < 64; i++) tn[i] = t1s[n * 64 + i] * sc[i] + sh[i];
        float a = bo[0];
        for (int j = 0; j < 64; j++) {
            float s = bt2[j];
#pragma unroll
            for (int i = 0; i < 64; i++) s += tn[i] * Wt2[i * 64 + j];
            a += fmaxf(s, 0.f) * Wo[j];
        }
        out[n] = sigf(a);
    }
}

// ---------------------------------------------------------------------------
extern "C" void kernel_launch(void* const* d_in, const int* in_sizes, int n_in,
                              void* d_out, int out_size)
{
    const float* operators = (const float*)d_in[0];
    const float* extra     = (const float*)d_in[1];
    const float* card      = (const float*)d_in[2];
    const float* cond1     = (const float*)d_in[3];
    const float* cond2     = (const float*)d_in[4];
    const int*   mapping   = (const int*)  d_in[5];
    const float* Wih1      = (const float*)d_in[6];
    const float* Whh1      = (const float*)d_in[7];
    const float* b1        = (const float*)d_in[8];
    const float* Wc        = (const float*)d_in[9];
    const float* bc        = (const float*)d_in[10];
    const float* g1        = (const float*)d_in[11];
    const float* be1       = (const float*)d_in[12];
    const float* Wih2      = (const float*)d_in[13];
    // d_in[14] = Whh2: unused (single step from zero state)
    const float* b2        = (const float*)d_in[15];
    const float* Win       = (const float*)d_in[16];
    const float* bin_      = (const float*)d_in[17];
    const float* Wlh       = (const float*)d_in[18];
    const float* blh       = (const float*)d_in[19];
    const float* Wrh       = (const float*)d_in[20];
    const float* brh       = (const float*)d_in[21];
    const float* g2        = (const float*)d_in[22];
    const float* be2       = (const float*)d_in[23];
    const float* Wt1       = (const float*)d_in[24];
    const float* bt1       = (const float*)d_in[25];
    const float* g3        = (const float*)d_in[26];
    const float* be3       = (const float*)d_in[27];
    const float* Wt2       = (const float*)d_in[28];
    const float* bt2       = (const float*)d_in[29];
    const float* Wo        = (const float*)d_in[30];
    const float* bo        = (const float*)d_in[31];
    float* out = (float*)d_out;

    const int LSTM1_SMEM = 144384;
    const int TREE_SMEM = 156160;
    cudaFuncSetAttribute(lstm1_kernel,
                         cudaFuncAttributeMaxDynamicSharedMemorySize, LSTM1_SMEM);
    cudaFuncSetAttribute(tree_kernel,
                         cudaFuncAttributeMaxDynamicSharedMemorySize, TREE_SMEM);

    // ordering: lstm1 at our idx 3 so ncu (-s 5) profiles it.
    wcat_kernel<<<160, 1024>>>(Wlh, Wrh);
    bb_kernel<<<1, 640>>>(blh, brh);
    b1copy_kernel<<<1, 512>>>(b1);
    lstm1_kernel<<<128, 256, LSTM1_SMEM>>>(cond1, cond2, Wih1, Whh1);
    lo_kernel<<<128, 256>>>(Wc, bc);
    bn1_final_kernel<<<1, 256>>>(g1, be1);
    prep_kernel<<<143, 128>>>(operators, extra, card, Wih2, b2, Win, bin_);
    tree_kernel<<<dim3(8, 5), 256, TREE_SMEM>>>(mapping);
    tail_kernel<<<1, 256>>>(g2, be2, Wt1, bt1, g3, be3, Wt2, bt2, Wo, bo, out);
}

// round 8
// speedup vs baseline: 2.3615x; 1.0444x over previous
#include <cuda_runtime.h>
#include <cstdint>

// Shapes: L=16, N=128, C=10, D=13, H=128, HID=64, F=88
#define DINL __device__ __forceinline__

// ------------------------- device scratch -------------------------
__device__ __align__(16) float g_h1[4096 * 128];   // LSTM1 final hidden
__device__ __align__(16) float g_lo[2048 * 64];    // lo pre-BN
__device__ __align__(16) float g_part[128 * 64];   // BN1 partial sums
__device__ __align__(16) float g_part2[128 * 64];  // BN1 partial sumsq
__device__ float g_sc1[64], g_sh1[64];             // BN1 scale/shift
__device__ __align__(16) float g_Wcat[256 * 640];  // [Wlh|Wrh] repacked
__device__ __align__(16) float g_bb[5 * 128];      // blh+brh combined
__device__ __align__(16) float g_b1c[512];         // b1 copy
__device__ float g_base[15 * 128];                 // per-step base vectors (a=0)
__device__ __align__(16) float g_h[2][128 * 128];  // tree h state (ping-pong)
__device__ __align__(16) float g_c[2][128 * 128];  // tree c state (ping-pong)
__device__ __align__(16) float g_P[128 * 640];     // tree projection per step
__device__ unsigned int g_bar_count;               // grid barrier (zero-init)
__device__ unsigned int g_bar_gen;

// ------------------------- helpers -------------------------
DINL float sigf(float x) { return __fdividef(1.f, 1.f + __expf(-x)); }
DINL float tanh_(float x) { return 2.f * sigf(2.f * x) - 1.f; }
DINL void fma2(unsigned long long& a, unsigned long long b, unsigned long long c) {
    asm("fma.rn.f32x2 %0, %1, %2, %0;" : "+l"(a) : "l"(b), "l"(c));
}
DINL void add2(unsigned long long& a, unsigned long long b) {
    asm("add.rn.f32x2 %0, %0, %1;" : "+l"(a) : "l"(b));
}
DINL unsigned long long dup2(float x) {
    unsigned long long r;
    asm("mov.b64 %0, {%1, %1};" : "=l"(r) : "f"(x));
    return r;
}
DINL float2 unp2(unsigned long long v) {
    float2 f;
    asm("mov.b64 {%0, %1}, %2;" : "=f"(f.x), "=f"(f.y) : "l"(v));
    return f;
}
DINL void cpasync16(uint32_t dst, const void* src) {
    asm volatile("cp.async.ca.shared.global [%0], [%1], 16;" :: "r"(dst), "l"(src) : "memory");
}
DINL void cp_commit() { asm volatile("cp.async.commit_group;" ::: "memory"); }
DINL void cp_wait1() { asm volatile("cp.async.wait_group 1;" ::: "memory"); }
DINL void cp_wait0() { asm volatile("cp.async.wait_group 0;" ::: "memory"); }

// Software grid barrier (sense via generation counter). 40 co-resident blocks.
DINL void grid_barrier(unsigned int nb) {
    __syncthreads();
    if (threadIdx.x == 0) {
        __threadfence();
        unsigned int gen = *(volatile unsigned int*)&g_bar_gen;
        if (atomicAdd(&g_bar_count, 1u) == nb - 1) {
            atomicExch(&g_bar_count, 0u);
            __threadfence();
            atomicExch(&g_bar_gen, gen + 1u);
        } else {
            while (*(volatile unsigned int*)&g_bar_gen == gen) {}
        }
        __threadfence();
    }
    __syncthreads();
}

// ---------------------------------------------------------------------------
// P1: repack Wcat[h, g*128+k] = h<128 ? Wlh[g,h,k] : Wrh[g,h-128,k]
// ---------------------------------------------------------------------------
__global__ void __launch_bounds__(1024) wcat_kernel(const float* __restrict__ Wlh,
                                                    const float* __restrict__ Wrh)
{
    int i = blockIdx.x * 1024 + threadIdx.x;
    if (i >= 256 * 640) return;
    int h = i / 640, col = i - h * 640;
    int g = col >> 7, k = col & 127;
    g_Wcat[i] = (h < 128) ? Wlh[g * 16384 + h * 128 + k]
                          : Wrh[g * 16384 + (h - 128) * 128 + k];
}

// P2: combined tree bias
__global__ void __launch_bounds__(640) bb_kernel(const float* __restrict__ blh,
                                                 const float* __restrict__ brh)
{
    int i = threadIdx.x;
    g_bb[i] = blh[i] + brh[i];
}

// P3: b1 copy + barrier reset
__global__ void __launch_bounds__(512) b1copy_kernel(const float* __restrict__ b1)
{
    int i = threadIdx.x;
    g_b1c[i] = b1[i];
    if (i == 0) { g_bar_count = 0u; }
}

// ---------------------------------------------------------------------------
// K1: LSTM1, per-gate warp split: block 512 = 16 warps.
// warp w: gate g4 = w>>2 (0=i,1=f,2=g,3=o), rows lr0 = (w&3)*8 .. +8.
// Each lane owns cols lane*4..+3 of its gate. 3-buffer cp.async pipeline,
// ONE __syncthreads per 16-k tile.  Wih resident in smem.
// smem (floats): z[32][144] 4608 | wihs 6656 | ws 3*8192 | gbF/G/O/C 4*4224
//   = 52736 floats = 210944 B.
// ---------------------------------------------------------------------------
DINL void stage_tile3(uint32_t ws_addr, const float* Whh, int tile, int buf, int tid) {
    const char* src = (const char*)Whh + (size_t)tile * 32768 + tid * 16;
    uint32_t dst = ws_addr + buf * 32768 + tid * 16;
#pragma unroll
    for (int p = 0; p < 4; p++)
        cpasync16(dst + p * 8192, src + p * 8192);
}

__global__ void __launch_bounds__(512) lstm1_kernel(
    const float* __restrict__ cond1, const float* __restrict__ cond2,
    const float* __restrict__ Wih, const float* __restrict__ Whh)
{
    extern __shared__ float smem[];
    float (*z)[144] = (float (*)[144])smem;                 // 4608
    float* wihs = smem + 4608;                              // 6656
    float* ws   = smem + 11264;                             // 24576 (3 x 8192)
    float (*gbF)[132] = (float (*)[132])(smem + 35840);
    float (*gbG)[132] = (float (*)[132])(smem + 40064);
    float (*gbO)[132] = (float (*)[132])(smem + 44288);
    float (*gbC)[132] = (float (*)[132])(smem + 48512);     // ends 52736
    uint32_t wih_addr = (uint32_t)__cvta_generic_to_shared(wihs);
    uint32_t ws_addr  = (uint32_t)__cvta_generic_to_shared(ws);

    const int tid = threadIdx.x, warp = tid >> 5, lane = tid & 31;
    const int g4 = warp >> 2;          // gate index
    const int lr0 = (warp & 3) * 8;    // 8 rows per warp
    const int brow0 = blockIdx.x * 32;

    // stage Wih (group A), tiles 0,1 (groups B,C)
    for (int i = tid; i < 1664; i += 512)
        cpasync16(wih_addr + i * 16, (const char*)Wih + i * 16);
    cp_commit();
    stage_tile3(ws_addr, Whh, 0, 0, tid); cp_commit();
    stage_tile3(ws_addr, Whh, 1, 1, tid); cp_commit();

    // zero h region and c state
    for (int i = tid; i < 4096; i += 512) z[i >> 7][i & 127] = 0.f;
    for (int i = tid; i < 4224; i += 512) (&gbC[0][0])[i] = 0.f;

    const float* src[8];
#pragma unroll
    for (int r = 0; r < 8; r++) {
        int gr = brow0 + lr0 + r;
        src[r] = (gr < 2048) ? (cond1 + (size_t)gr * 130)
                             : (cond2 + (size_t)(gr - 2048) * 130);
    }
    unsigned long long bias0, bias1;
    {
        ulonglong2 bb = *(const ulonglong2*)(g_b1c + g4 * 128 + lane * 4);
        bias0 = bb.x; bias1 = bb.y;
    }

    for (int t = 0; t < 10; t++) {
        if (g4 == 0) {  // i-warps own x loads for their 8 rows
            for (int idx = lane; idx < 104; idx += 32) {
                int r = idx / 13, c = idx - r * 13;
                z[lr0 + r][128 + c] = src[r][t * 13 + c];
            }
        }
        unsigned long long acc[8][2];
#pragma unroll
        for (int r = 0; r < 8; r++) { acc[r][0] = bias0; acc[r][1] = bias1; }

        // h @ Whh: 8 tiles of 16 k, 3-buffer pipeline, 1 sync per tile
        for (int kt = 0; kt < 8; kt++) {
            cp_wait1();
            __syncthreads();   // tile kt staged & visible; h/x visible at kt==0
            const ulonglong2* W = (const ulonglong2*)(ws + ((t * 8 + kt) % 3) * 8192);
#pragma unroll
            for (int kk4 = 0; kk4 < 4; kk4++) {
                float4 a4[8];
#pragma unroll
                for (int r = 0; r < 8; r++)
                    a4[r] = *(const float4*)&z[lr0 + r][kt * 16 + kk4 * 4];
#pragma unroll
                for (int q = 0; q < 4; q++) {
                    ulonglong2 w = W[(kk4 * 4 + q) * 128 + g4 * 32 + lane];
#pragma unroll
                    for (int r = 0; r < 8; r++) {
                        float zv = (q == 0) ? a4[r].x : (q == 1) ? a4[r].y
                                 : (q == 2) ? a4[r].z : a4[r].w;
                        unsigned long long a = dup2(zv);
                        fma2(acc[r][0], a, w.x);
                        fma2(acc[r][1], a, w.y);
                    }
                }
            }
            stage_tile3(ws_addr, Whh, (kt + 2) & 7, (t * 8 + kt + 2) % 3, tid);
            cp_commit();
        }

        // x @ Wih from resident smem
        {
            const ulonglong2* Wx = (const ulonglong2*)wihs;
#pragma unroll 4
            for (int k = 0; k < 13; k++) {
                ulonglong2 w = Wx[k * 128 + g4 * 32 + lane];
#pragma unroll
                for (int r = 0; r < 8; r++) {
                    unsigned long long a = dup2(z[lr0 + r][128 + k]);
                    fma2(acc[r][0], a, w.x);
                    fma2(acc[r][1], a, w.y);
                }
            }
        }

        // publish f,g,o pre-activations
        if (g4 == 1) {
#pragma unroll
            for (int r = 0; r < 8; r++)
                *(ulonglong2*)&gbF[lr0 + r][lane * 4] = make_ulonglong2(acc[r][0], acc[r][1]);
        } else if (g4 == 2) {
#pragma unroll
            for (int r = 0; r < 8; r++)
                *(ulonglong2*)&gbG[lr0 + r][lane * 4] = make_ulonglong2(acc[r][0], acc[r][1]);
        } else if (g4 == 3) {
#pragma unroll
            for (int r = 0; r < 8; r++)
                *(ulonglong2*)&gbO[lr0 + r][lane * 4] = make_ulonglong2(acc[r][0], acc[r][1]);
        }
        __syncthreads();

        if (g4 == 0) {  // cell update, c state in smem
#pragma unroll
            for (int r = 0; r < 8; r++) {
                ulonglong2 fu = *(const ulonglong2*)&gbF[lr0 + r][lane * 4];
                ulonglong2 gu = *(const ulonglong2*)&gbG[lr0 + r][lane * 4];
                ulonglong2 ou = *(const ulonglong2*)&gbO[lr0 + r][lane * 4];
                float4 cold = *(const float4*)&gbC[lr0 + r][lane * 4];
                float2 i01 = unp2(acc[r][0]), i23 = unp2(acc[r][1]);
                float2 f01 = unp2(fu.x), f23 = unp2(fu.y);
                float2 G01 = unp2(gu.x), G23 = unp2(gu.y);
                float2 o01 = unp2(ou.x), o23 = unp2(ou.y);
                float iv[4] = {i01.x, i01.y, i23.x, i23.y};
                float fv[4] = {f01.x, f01.y, f23.x, f23.y};
                float gv[4] = {G01.x, G01.y, G23.x, G23.y};
                float ov[4] = {o01.x, o01.y, o23.x, o23.y};
                float cv[4] = {cold.x, cold.y, cold.z, cold.w};
                float hv[4], cn[4];
#pragma unroll
                for (int q = 0; q < 4; q++) {
                    float c = sigf(fv[q]) * cv[q] + sigf(iv[q]) * tanh_(gv[q]);
                    cn[q] = c;
                    hv[q] = sigf(ov[q]) * tanh_(c);
                }
                *(float4*)&gbC[lr0 + r][lane * 4] = make_float4(cn[0], cn[1], cn[2], cn[3]);
                *(float4*)&z[lr0 + r][lane * 4]  = make_float4(hv[0], hv[1], hv[2], hv[3]);
            }
        }
        // visibility of new h/x: next iteration's kt==0 __syncthreads
    }

    cp_wait0();       // retire stray prefetch groups
    __syncthreads();
    for (int i = tid; i < 4096; i += 512)
        g_h1[(size_t)(brow0 + (i >> 7)) * 128 + (i & 127)] = z[i >> 7][i & 127];
}

// ---------------------------------------------------------------------------
// K2: lo = 0.5*(relu(h1@Wc+bc)+relu(h2@Wc+bc)) (2048x64), 16 rows/block,
// plus deterministic per-block BN1 partial sums.
// ---------------------------------------------------------------------------
__global__ void __launch_bounds__(256) lo_kernel(const float* __restrict__ Wc,
                                                 const float* __restrict__ bc)
{
    __shared__ float ha[16][128], hb[16][128];
    __shared__ float red[256], red2[256];
    int tid = threadIdx.x, r0 = blockIdx.x * 16;
    for (int i = tid; i < 16 * 128; i += 256) {
        int r = i >> 7, h = i & 127;
        ha[r][h] = g_h1[(size_t)(r0 + r) * 128 + h];
        hb[r][h] = g_h1[(size_t)(2048 + r0 + r) * 128 + h];
    }
    __syncthreads();
    int j = tid & 63;
    float ps = 0.f, ps2 = 0.f;
#pragma unroll
    for (int rg = 0; rg < 4; rg++) {
        int r = (tid >> 6) + rg * 4;
        float s1 = bc[j], s2 = s1;
        for (int h = 0; h < 128; h++) {
            float w = Wc[h * 64 + j];
            s1 += ha[r][h] * w;
            s2 += hb[r][h] * w;
        }
        float v = 0.5f * (fmaxf(s1, 0.f) + fmaxf(s2, 0.f));
        g_lo[(size_t)(r0 + r) * 64 + j] = v;
        ps += v; ps2 += v * v;
    }
    red[tid] = ps; red2[tid] = ps2;
    __syncthreads();
    if (tid < 64) {
        for (int p = 1; p < 4; p++) { ps += red[tid + 64 * p]; ps2 += red2[tid + 64 * p]; }
        g_part[blockIdx.x * 64 + tid] = ps;
        g_part2[blockIdx.x * 64 + tid] = ps2;
    }
}

// K2b: finalize BN1 stats -> scale/shift
__global__ void __launch_bounds__(256) bn1_final_kernel(const float* __restrict__ g,
                                                        const float* __restrict__ be)
{
    __shared__ float r1[256], r2[256];
    int tid = threadIdx.x, j = tid & 63, part = tid >> 6;
    float s = 0.f, s2 = 0.f;
    for (int b = part; b < 128; b += 4) { s += g_part[b * 64 + j]; s2 += g_part2[b * 64 + j]; }
    r1[tid] = s; r2[tid] = s2;
    __syncthreads();
    if (tid < 64) {
        for (int p = 1; p < 4; p++) { s += r1[tid + 64 * p]; s2 += r2[tid + 64 * p]; }
        float m = s * (1.f / 2048.f);
        float v = s2 * (1.f / 2048.f) - m * m;
        float sc = g[tid] * rsqrtf(v + 1e-5f);
        g_sc1[tid] = sc;
        g_sh1[tid] = be[tid] - m * sc;
    }
}

// ---------------------------------------------------------------------------
// K4: prep = LSTM2 single step from zero state (blocks 0..127) + base vectors
// (blocks 128..142).  block 128 threads.
// ---------------------------------------------------------------------------
__global__ void __launch_bounds__(128) prep_kernel(
    const float* __restrict__ ops, const float* __restrict__ ext,
    const float* __restrict__ card, const float* __restrict__ Wih2,
    const float* __restrict__ b2, const float* __restrict__ Win,
    const float* __restrict__ bin_)
{
    __shared__ float x[88];
    int b = blockIdx.x, k = threadIdx.x;
    int row = (b < 128) ? (15 * 128 + b) : ((b - 128) * 128 + 0);
    if (k < 15)      x[k] = ops[row * 15 + k];
    else if (k < 22) x[k] = ext[row * 7 + (k - 15)];
    else if (k < 24) x[k] = card[row * 2 + (k - 22)];
    else if (k < 88) x[k] = g_lo[(size_t)row * 64 + (k - 24)] * g_sc1[k - 24] + g_sh1[k - 24];
    __syncthreads();

    if (b < 128) {
        float gi = b2[k], gg = b2[256 + k], go = b2[384 + k];
        for (int j = 0; j < 88; j++) {
            float xv = x[j];
            const float* w = Wih2 + j * 512;
            gi += xv * w[k];
            gg += xv * w[256 + k];
            go += xv * w[384 + k];
        }
        float c = sigf(gi) * tanh_(gg);  // sig(f)*c_prev = 0
        float h = sigf(go) * tanh_(c);
        g_h[0][b * 128 + k] = h;
        g_c[0][b * 128 + k] = c;
    } else {
        int l = b - 128;
        float s = bin_[k];
        for (int j = 0; j < 88; j++) s += x[j] * Win[j * 128 + k];
        g_base[(14 - l) * 128 + k] = s;
    }
}

// ---------------------------------------------------------------------------
// K5: fused tree scan — 15 steps, persistent. grid (8,5)=40 blocks, block 512.
// Full 256x128 W slice staged once into smem.  Thread layout: q = tid>>7
// (k quarter of 64), warp4 rows r0=warp4*4, lane cols lane*4.
// smem (floats): Wsm 32768 | A[16][264] 4224 | red 3*2048 = 43136 f = 172544 B.
// ---------------------------------------------------------------------------
__global__ void __launch_bounds__(512) tree_kernel(const int* __restrict__ mapping)
{
    const unsigned int NB = 40;
    extern __shared__ float smem[];
    float* Wsm = smem;
    float (*A)[264] = (float (*)[264])(smem + 32768);
    float* red = smem + 36992;
    uint32_t wsm_addr = (uint32_t)__cvta_generic_to_shared(Wsm);

    int tid = threadIdx.x, bx = blockIdx.x, g = blockIdx.y;
    int bid = g * 8 + bx;

    // stage W slice: Wsm[k][c] = g_Wcat[k*640 + g*128 + c]; row = 32 x 16B
    for (int i = tid; i < 8192; i += 512)
        cpasync16(wsm_addr + i * 16,
                  g_Wcat + (size_t)(i >> 5) * 640 + g * 128 + (i & 31) * 4);
    cp_commit();
    cp_wait0();
    __syncthreads();

    const int q = tid >> 7, t128 = tid & 127;
    const int warp4 = t128 >> 5, lane = t128 & 31;
    const int r0 = warp4 * 4;
    const int k0 = q * 64;
    const ulonglong2* Wu2 = (const ulonglong2*)Wsm;

    for (int s = 0; s < 15; s++) {
        int lvl = 14 - s, p = s & 1;
        const float* __restrict__ hprev = g_h[p];

        // gather A = [lh|rh] rows for this block's 16 n
        for (int i = tid; i < 16 * 256; i += 512) {
            int r = i >> 8, h = i & 255;
            int n = bx * 16 + r;
            int mp = mapping[(lvl * 128 + n) * 2 + (h >> 7)];
            A[r][h] = (mp > 0) ? hprev[(mp - 1) * 128 + (h & 127)] : 0.f;
        }
        __syncthreads();

        unsigned long long acc[8];
#pragma unroll
        for (int j = 0; j < 8; j++) acc[j] = 0ull;

#pragma unroll 4
        for (int kk4 = 0; kk4 < 16; kk4++) {
            float4 a4[4];
#pragma unroll
            for (int r = 0; r < 4; r++)
                a4[r] = *(const float4*)&A[r0 + r][k0 + kk4 * 4];
#pragma unroll
            for (int qq = 0; qq < 4; qq++) {
                int k = k0 + kk4 * 4 + qq;
                ulonglong2 w = Wu2[k * 32 + lane];
#pragma unroll
                for (int r = 0; r < 4; r++) {
                    float av = (qq == 0) ? a4[r].x : (qq == 1) ? a4[r].y
                             : (qq == 2) ? a4[r].z : a4[r].w;
                    unsigned long long v = dup2(av);
                    fma2(acc[r * 2], v, w.x);
                    fma2(acc[r * 2 + 1], v, w.y);
                }
            }
        }

        if (q > 0) {
#pragma unroll
            for (int r = 0; r < 4; r++)
                *(ulonglong2*)&red[(q - 1) * 2048 + (r0 + r) * 128 + lane * 4] =
                    make_ulonglong2(acc[r * 2], acc[r * 2 + 1]);
        }
        __syncthreads();
        if (q == 0) {
#pragma unroll
            for (int r = 0; r < 4; r++) {
#pragma unroll
                for (int j = 0; j < 3; j++) {
                    ulonglong2 p2 = *(const ulonglong2*)&red[j * 2048 + (r0 + r) * 128 + lane * 4];
                    add2(acc[r * 2], p2.x);
                    add2(acc[r * 2 + 1], p2.y);
                }
                *(ulonglong2*)(g_P + (size_t)(bx * 16 + r0 + r) * 640 + g * 128 + lane * 4) =
                    make_ulonglong2(acc[r * 2], acc[r * 2 + 1]);
            }
        }

        grid_barrier(NB);

        // pointwise cell update over 128x128 elems, 20480 threads
        for (int idx = bid * 512 + tid; idx < 16384; idx += 20480) {
            int n = idx >> 7, k = idx & 127;
            int mp0 = mapping[(lvl * 128 + n) * 2 + 0];
            int mp1 = mapping[(lvl * 128 + n) * 2 + 1];
            float lc = (mp0 > 0) ? g_c[p][(mp0 - 1) * 128 + k] : 0.f;
            float rc = (mp1 > 0) ? g_c[p][(mp1 - 1) * 128 + k] : 0.f;
            float bse = g_base[s * 128 + k];
            const float* P = g_P + (size_t)n * 640;
            float pre[5];
#pragma unroll
            for (int qq = 0; qq < 5; qq++)
                pre[qq] = bse + P[qq * 128 + k] + g_bb[qq * 128 + k];
            float i = sigf(pre[0]), lf = sigf(pre[1]), rf = sigf(pre[2]);
            float u = tanh_(pre[3]), o = sigf(pre[4]);
            float c = i * u + lf * lc + rf * rc;
            g_c[1 - p][n * 128 + k] = c;
            g_h[1 - p][n * 128 + k] = o * tanh_(c);
        }

        grid_barrier(NB);
    }
}

// ---------------------------------------------------------------------------
// K6: fused tail: BN2 -> t1 -> BN3 -> t2 -> sigmoid output.  One block, 256.
// ---------------------------------------------------------------------------
__global__ void __launch_bounds__(256) tail_kernel(
    const float* __restrict__ g2, const float* __restrict__ be2,
    const float* __restrict__ Wt1, const float* __restrict__ bt1,
    const float* __restrict__ g3, const float* __restrict__ be3,
    const float* __restrict__ Wt2, const float* __restrict__ bt2,
    const float* __restrict__ Wo, const float* __restrict__ bo,
    float* __restrict__ out)
{
    __shared__ float t1s[128 * 64];  // 32KB
    __shared__ float sc[128], sh[128];
    __shared__ float red[256], red2[256];
    int tid = threadIdx.x;

    // BN2 stats over g_h[1] (128x128)
    {
        int col = tid & 127, part = tid >> 7;
        float s = 0.f, s2 = 0.f;
        for (int r = part; r < 128; r += 2) {
            float v = g_h[1][r * 128 + col];
            s += v; s2 += v * v;
        }
        red[tid] = s; red2[tid] = s2;
        __syncthreads();
        if (tid < 128) {
            s = red[tid] + red[tid + 128];
            s2 = red2[tid] + red2[tid + 128];
            float m = s * (1.f / 128.f);
            float v = s2 * (1.f / 128.f) - m * m;
            float scl = g2[tid] * rsqrtf(v + 1e-5f);
            sc[tid] = scl;
            sh[tid] = be2[tid] - m * scl;
        }
        __syncthreads();
    }

    // t1 = relu(bn2(h) @ Wt1 + bt1)  (128x64)
    for (int o = tid; o < 8192; o += 256) {
        int n = o >> 6, j = o & 63;
        float acc = bt1[j];
        for (int h = 0; h < 128; h++)
            acc += (g_h[1][n * 128 + h] * sc[h] + sh[h]) * Wt1[h * 64 + j];
        t1s[o] = fmaxf(acc, 0.f);
    }
    __syncthreads();

    // BN3 stats over t1s (128x64)
    {
        int col = tid & 63, part = tid >> 6;
        float s = 0.f, s2 = 0.f;
        for (int r = part; r < 128; r += 4) {
            float v = t1s[r * 64 + col];
            s += v; s2 += v * v;
        }
        red[tid] = s; red2[tid] = s2;
        __syncthreads();
        if (tid < 64) {
            for (int p = 1; p < 4; p++) { s += red[tid + 64 * p]; s2 += red2[tid + 64 * p]; }
            float m = s * (1.f / 128.f);
            float v = s2 * (1.f / 128.f) - m * m;
            float scl = g3[tid] * rsqrtf(v + 1e-5f);
            sc[tid] = scl;
            sh[tid] = be3[tid] - m * scl;
        }
        __syncthreads();
    }

    // t2 = relu(bn3(t1)@Wt2+bt2); out = sigmoid(t2@Wo+bo)
    if (tid < 128) {
        int n = tid;
        float tn[64];
#pragma unroll
        for (int i = 0; i < 64; i++) tn[i] = t1s[n * 64 + i] * sc[i] + sh[i];
        float a = bo[0];
        for (int j = 0; j < 64; j++) {
            float s = bt2[j];
#pragma unroll
            for (int i = 0; i < 64; i++) s += tn[i] * Wt2[i * 64 + j];
            a += fmaxf(s, 0.f) * Wo[j];
        }
        out[n] = sigf(a);
    }
}

// ---------------------------------------------------------------------------
extern "C" void kernel_launch(void* const* d_in, const int* in_sizes, int n_in,
                              void* d_out, int out_size)
{
    const float* operators = (const float*)d_in[0];
    const float* extra     = (const float*)d_in[1];
    const float* card      = (const float*)d_in[2];
    const float* cond1     = (const float*)d_in[3];
    const float* cond2     = (const float*)d_in[4];
    const int*   mapping   = (const int*)  d_in[5];
    const float* Wih1      = (const float*)d_in[6];
    const float* Whh1      = (const float*)d_in[7];
    const float* b1        = (const float*)d_in[8];
    const float* Wc        = (const float*)d_in[9];
    const float* bc        = (const float*)d_in[10];
    const float* g1        = (const float*)d_in[11];
    const float* be1       = (const float*)d_in[12];
    const float* Wih2      = (const float*)d_in[13];
    // d_in[14] = Whh2: unused (single step from zero state)
    const float* b2        = (const float*)d_in[15];
    const float* Win       = (const float*)d_in[16];
    const float* bin_      = (const float*)d_in[17];
    const float* Wlh       = (const float*)d_in[18];
    const float* blh       = (const float*)d_in[19];
    const float* Wrh       = (const float*)d_in[20];
    const float* brh       = (const float*)d_in[21];
    const float* g2        = (const float*)d_in[22];
    const float* be2       = (const float*)d_in[23];
    const float* Wt1       = (const float*)d_in[24];
    const float* bt1       = (const float*)d_in[25];
    const float* g3        = (const float*)d_in[26];
    const float* be3       = (const float*)d_in[27];
    const float* Wt2       = (const float*)d_in[28];
    const float* bt2       = (const float*)d_in[29];
    const float* Wo        = (const float*)d_in[30];
    const float* bo        = (const float*)d_in[31];
    float* out = (float*)d_out;

    const int LSTM1_SMEM = 52736 * 4;   // 210944 B
    const int TREE_SMEM  = 43136 * 4;   // 172544 B
    cudaFuncSetAttribute(lstm1_kernel,
                         cudaFuncAttributeMaxDynamicSharedMemorySize, LSTM1_SMEM);
    cudaFuncSetAttribute(tree_kernel,
                         cudaFuncAttributeMaxDynamicSharedMemorySize, TREE_SMEM);

    // ordering: lstm1 at our idx 3 so ncu (-s 5) profiles it.
    wcat_kernel<<<160, 1024>>>(Wlh, Wrh);
    bb_kernel<<<1, 640>>>(blh, brh);
    b1copy_kernel<<<1, 512>>>(b1);
    lstm1_kernel<<<128, 512, LSTM1_SMEM>>>(cond1, cond2, Wih1, Whh1);
    lo_kernel<<<128, 256>>>(Wc, bc);
    bn1_final_kernel<<<1, 256>>>(g1, be1);
    prep_kernel<<<143, 128>>>(operators, extra, card, Wih2, b2, Win, bin_);
    tree_kernel<<<dim3(8, 5), 512, TREE_SMEM>>>(mapping);
    tail_kernel<<<1, 256>>>(g2, be2, Wt1, bt1, g3, be3, Wt2, bt2, Wo, bo, out);
}

// round 9
// speedup vs baseline: 2.3803x; 1.0080x over previous
#include <cuda_runtime.h>
#include <cstdint>

// Shapes: L=16, N=128, C=10, D=13, H=128, HID=64, F=88
#define DINL __device__ __forceinline__

// ------------------------- device scratch -------------------------
__device__ __align__(16) float g_h1[4096 * 128];   // LSTM1 final hidden
__device__ __align__(16) float g_lo[2048 * 64];    // lo pre-BN
__device__ __align__(16) float g_part[128 * 64];   // BN1 partial sums
__device__ __align__(16) float g_part2[128 * 64];  // BN1 partial sumsq
__device__ __align__(16) float g_Wcat[256 * 640];  // [Wlh|Wrh] repacked
__device__ __align__(16) float g_bb[5 * 128];      // blh+brh combined
__device__ float g_base[15 * 128];                 // per-step base vectors (a=0)
__device__ __align__(16) float g_h[2][128 * 128];  // tree h state (ping-pong)
__device__ __align__(16) float g_c[2][128 * 128];  // tree c state (ping-pong)
__device__ __align__(16) float g_P[128 * 640];     // tree projection per step
__device__ unsigned int g_bar_count;               // grid barrier (self-restoring 0)
__device__ unsigned int g_bar_gen;

// ------------------------- helpers -------------------------
DINL float sigf(float x) { return __fdividef(1.f, 1.f + __expf(-x)); }
DINL float tanh_(float x) { return 2.f * sigf(2.f * x) - 1.f; }
DINL void fma2(unsigned long long& a, unsigned long long b, unsigned long long c) {
    asm("fma.rn.f32x2 %0, %1, %2, %0;" : "+l"(a) : "l"(b), "l"(c));
}
DINL void add2(unsigned long long& a, unsigned long long b) {
    asm("add.rn.f32x2 %0, %0, %1;" : "+l"(a) : "l"(b));
}
DINL unsigned long long dup2(float x) {
    unsigned long long r;
    asm("mov.b64 %0, {%1, %1};" : "=l"(r) : "f"(x));
    return r;
}
DINL float2 unp2(unsigned long long v) {
    float2 f;
    asm("mov.b64 {%0, %1}, %2;" : "=f"(f.x), "=f"(f.y) : "l"(v));
    return f;
}
DINL void cpasync16(uint32_t dst, const void* src) {
    asm volatile("cp.async.ca.shared.global [%0], [%1], 16;" :: "r"(dst), "l"(src) : "memory");
}
DINL void cp_commit() { asm volatile("cp.async.commit_group;" ::: "memory"); }
DINL void cp_wait1() { asm volatile("cp.async.wait_group 1;" ::: "memory"); }
DINL void cp_wait0() { asm volatile("cp.async.wait_group 0;" ::: "memory"); }

// Software grid barrier. 40 co-resident blocks. Leaves g_bar_count == 0.
DINL void grid_barrier(unsigned int nb) {
    __syncthreads();
    if (threadIdx.x == 0) {
        __threadfence();
        unsigned int gen = *(volatile unsigned int*)&g_bar_gen;
        if (atomicAdd(&g_bar_count, 1u) == nb - 1) {
            atomicExch(&g_bar_count, 0u);
            __threadfence();
            atomicExch(&g_bar_gen, gen + 1u);
        } else {
            while (*(volatile unsigned int*)&g_bar_gen == gen) {}
        }
        __threadfence();
    }
    __syncthreads();
}

// ---------------------------------------------------------------------------
// K1: LSTM1 (+ fused Wcat repack + bb combine prologue).
// Per-gate warp split: block 512 = 16 warps; warp w: gate g4=w>>2, rows
// lr0=(w&3)*8.  3-buffer cp.async pipeline, one __syncthreads per 16-k tile.
// smem (floats): z[32][144] 4608 | wihs 6656 | ws 3*8192 | gbF/G/O/C 4*4224
//   = 52736 floats = 210944 B.
// ---------------------------------------------------------------------------
DINL void stage_tile3(uint32_t ws_addr, const float* Whh, int tile, int buf, int tid) {
    const char* src = (const char*)Whh + (size_t)tile * 32768 + tid * 16;
    uint32_t dst = ws_addr + buf * 32768 + tid * 16;
#pragma unroll
    for (int p = 0; p < 4; p++)
        cpasync16(dst + p * 8192, src + p * 8192);
}

__global__ void __launch_bounds__(512) lstm1_kernel(
    const float* __restrict__ cond1, const float* __restrict__ cond2,
    const float* __restrict__ Wih, const float* __restrict__ Whh,
    const float* __restrict__ b1,
    const float* __restrict__ Wlh, const float* __restrict__ Wrh,
    const float* __restrict__ blh, const float* __restrict__ brh)
{
    extern __shared__ float smem[];
    float (*z)[144] = (float (*)[144])smem;                 // 4608
    float* wihs = smem + 4608;                              // 6656
    float* ws   = smem + 11264;                             // 24576 (3 x 8192)
    float (*gbF)[132] = (float (*)[132])(smem + 35840);
    float (*gbG)[132] = (float (*)[132])(smem + 40064);
    float (*gbO)[132] = (float (*)[132])(smem + 44288);
    float (*gbC)[132] = (float (*)[132])(smem + 48512);     // ends 52736
    uint32_t wih_addr = (uint32_t)__cvta_generic_to_shared(wihs);
    uint32_t ws_addr  = (uint32_t)__cvta_generic_to_shared(ws);

    const int tid = threadIdx.x, warp = tid >> 5, lane = tid & 31;
    const int g4 = warp >> 2;          // gate index 0=i,1=f,2=g,3=o
    const int lr0 = (warp & 3) * 8;    // 8 rows per warp
    const int brow0 = blockIdx.x * 32;

    // stage Wih (group A), Whh tiles 0,1 (groups B,C)
    for (int i = tid; i < 1664; i += 512)
        cpasync16(wih_addr + i * 16, (const char*)Wih + i * 16);
    cp_commit();
    stage_tile3(ws_addr, Whh, 0, 0, tid); cp_commit();
    stage_tile3(ws_addr, Whh, 1, 1, tid); cp_commit();

    // fused prologue work (runs under cp.async latency):
    // Wcat repack slice: this block owns 1280 of 163840 elems
    {
        int i0 = blockIdx.x * 1280;
#pragma unroll
        for (int it = 0; it < 3; it++) {
            int i = i0 + it * 512 + tid;
            if (it * 512 + tid < 1280) {
                int h = i / 640, col = i - h * 640;
                int gg = col >> 7, k = col & 127;
                g_Wcat[i] = (h < 128) ? Wlh[gg * 16384 + h * 128 + k]
                                      : Wrh[gg * 16384 + (h - 128) * 128 + k];
            }
        }
        if (blockIdx.x == 0 && tid < 640) g_bb[tid] = blh[tid] + brh[tid];
    }

    // zero h region and c state
    for (int i = tid; i < 4096; i += 512) z[i >> 7][i & 127] = 0.f;
    for (int i = tid; i < 4224; i += 512) (&gbC[0][0])[i] = 0.f;

    const float* src[8];
#pragma unroll
    for (int r = 0; r < 8; r++) {
        int gr = brow0 + lr0 + r;
        src[r] = (gr < 2048) ? (cond1 + (size_t)gr * 130)
                             : (cond2 + (size_t)(gr - 2048) * 130);
    }
    unsigned long long bias0, bias1;
    {
        ulonglong2 bb = *(const ulonglong2*)(b1 + g4 * 128 + lane * 4);
        bias0 = bb.x; bias1 = bb.y;
    }

    for (int t = 0; t < 10; t++) {
        if (g4 == 0) {  // i-warps own x loads for their 8 rows
            for (int idx = lane; idx < 104; idx += 32) {
                int r = idx / 13, c = idx - r * 13;
                z[lr0 + r][128 + c] = src[r][t * 13 + c];
            }
        }
        unsigned long long acc[8][2];
#pragma unroll
        for (int r = 0; r < 8; r++) { acc[r][0] = bias0; acc[r][1] = bias1; }

        // h @ Whh: 8 tiles of 16 k, 3-buffer pipeline, 1 sync per tile
        for (int kt = 0; kt < 8; kt++) {
            cp_wait1();
            __syncthreads();   // tile kt staged & visible; h/x visible at kt==0
            const ulonglong2* W = (const ulonglong2*)(ws + ((t * 8 + kt) % 3) * 8192);
#pragma unroll
            for (int kk4 = 0; kk4 < 4; kk4++) {
                float4 a4[8];
#pragma unroll
                for (int r = 0; r < 8; r++)
                    a4[r] = *(const float4*)&z[lr0 + r][kt * 16 + kk4 * 4];
#pragma unroll
                for (int q = 0; q < 4; q++) {
                    ulonglong2 w = W[(kk4 * 4 + q) * 128 + g4 * 32 + lane];
#pragma unroll
                    for (int r = 0; r < 8; r++) {
                        float zv = (q == 0) ? a4[r].x : (q == 1) ? a4[r].y
                                 : (q == 2) ? a4[r].z : a4[r].w;
                        unsigned long long a = dup2(zv);
                        fma2(acc[r][0], a, w.x);
                        fma2(acc[r][1], a, w.y);
                    }
                }
            }
            stage_tile3(ws_addr, Whh, (kt + 2) & 7, (t * 8 + kt + 2) % 3, tid);
            cp_commit();
        }

        // x @ Wih from resident smem
        {
            const ulonglong2* Wx = (const ulonglong2*)wihs;
#pragma unroll 4
            for (int k = 0; k < 13; k++) {
                ulonglong2 w = Wx[k * 128 + g4 * 32 + lane];
#pragma unroll
                for (int r = 0; r < 8; r++) {
                    unsigned long long a = dup2(z[lr0 + r][128 + k]);
                    fma2(acc[r][0], a, w.x);
                    fma2(acc[r][1], a, w.y);
                }
            }
        }

        // publish f,g,o pre-activations
        if (g4 == 1) {
#pragma unroll
            for (int r = 0; r < 8; r++)
                *(ulonglong2*)&gbF[lr0 + r][lane * 4] = make_ulonglong2(acc[r][0], acc[r][1]);
        } else if (g4 == 2) {
#pragma unroll
            for (int r = 0; r < 8; r++)
                *(ulonglong2*)&gbG[lr0 + r][lane * 4] = make_ulonglong2(acc[r][0], acc[r][1]);
        } else if (g4 == 3) {
#pragma unroll
            for (int r = 0; r < 8; r++)
                *(ulonglong2*)&gbO[lr0 + r][lane * 4] = make_ulonglong2(acc[r][0], acc[r][1]);
        }
        __syncthreads();

        if (g4 == 0) {  // cell update, c state in smem
#pragma unroll
            for (int r = 0; r < 8; r++) {
                ulonglong2 fu = *(const ulonglong2*)&gbF[lr0 + r][lane * 4];
                ulonglong2 gu = *(const ulonglong2*)&gbG[lr0 + r][lane * 4];
                ulonglong2 ou = *(const ulonglong2*)&gbO[lr0 + r][lane * 4];
                float4 cold = *(const float4*)&gbC[lr0 + r][lane * 4];
                float2 i01 = unp2(acc[r][0]), i23 = unp2(acc[r][1]);
                float2 f01 = unp2(fu.x), f23 = unp2(fu.y);
                float2 G01 = unp2(gu.x), G23 = unp2(gu.y);
                float2 o01 = unp2(ou.x), o23 = unp2(ou.y);
                float iv[4] = {i01.x, i01.y, i23.x, i23.y};
                float fv[4] = {f01.x, f01.y, f23.x, f23.y};
                float gv[4] = {G01.x, G01.y, G23.x, G23.y};
                float ov[4] = {o01.x, o01.y, o23.x, o23.y};
                float cv[4] = {cold.x, cold.y, cold.z, cold.w};
                float hv[4], cn[4];
#pragma unroll
                for (int q = 0; q < 4; q++) {
                    float c = sigf(fv[q]) * cv[q] + sigf(iv[q]) * tanh_(gv[q]);
                    cn[q] = c;
                    hv[q] = sigf(ov[q]) * tanh_(c);
                }
                *(float4*)&gbC[lr0 + r][lane * 4] = make_float4(cn[0], cn[1], cn[2], cn[3]);
                *(float4*)&z[lr0 + r][lane * 4]  = make_float4(hv[0], hv[1], hv[2], hv[3]);
            }
        }
        // visibility of new h/x: next iteration's kt==0 __syncthreads
    }

    cp_wait0();       // retire stray prefetch groups
    __syncthreads();
    for (int i = tid; i < 4096; i += 512)
        g_h1[(size_t)(brow0 + (i >> 7)) * 128 + (i & 127)] = z[i >> 7][i & 127];
}

// ---------------------------------------------------------------------------
// K2: lo = 0.5*(relu(h1@Wc+bc)+relu(h2@Wc+bc)) (2048x64), 16 rows/block,
// plus deterministic per-block BN1 partial sums.
// ---------------------------------------------------------------------------
__global__ void __launch_bounds__(256) lo_kernel(const float* __restrict__ Wc,
                                                 const float* __restrict__ bc)
{
    __shared__ float ha[16][128], hb[16][128];
    __shared__ float red[256], red2[256];
    int tid = threadIdx.x, r0 = blockIdx.x * 16;
    for (int i = tid; i < 16 * 128; i += 256) {
        int r = i >> 7, h = i & 127;
        ha[r][h] = g_h1[(size_t)(r0 + r) * 128 + h];
        hb[r][h] = g_h1[(size_t)(2048 + r0 + r) * 128 + h];
    }
    __syncthreads();
    int j = tid & 63;
    float ps = 0.f, ps2 = 0.f;
#pragma unroll
    for (int rg = 0; rg < 4; rg++) {
        int r = (tid >> 6) + rg * 4;
        float s1 = bc[j], s2 = s1;
        for (int h = 0; h < 128; h++) {
            float w = Wc[h * 64 + j];
            s1 += ha[r][h] * w;
            s2 += hb[r][h] * w;
        }
        float v = 0.5f * (fmaxf(s1, 0.f) + fmaxf(s2, 0.f));
        g_lo[(size_t)(r0 + r) * 64 + j] = v;
        ps += v; ps2 += v * v;
    }
    red[tid] = ps; red2[tid] = ps2;
    __syncthreads();
    if (tid < 64) {
        for (int p = 1; p < 4; p++) { ps += red[tid + 64 * p]; ps2 += red2[tid + 64 * p]; }
        g_part[blockIdx.x * 64 + tid] = ps;
        g_part2[blockIdx.x * 64 + tid] = ps2;
    }
}

// ---------------------------------------------------------------------------
// K3: prep = redundant BN1 finalize (per block, deterministic) + LSTM2 single
// step from zero state (blocks 0..127) + base vectors (blocks 128..142).
// ---------------------------------------------------------------------------
__global__ void __launch_bounds__(128) prep_kernel(
    const float* __restrict__ ops, const float* __restrict__ ext,
    const float* __restrict__ card, const float* __restrict__ Wih2,
    const float* __restrict__ b2, const float* __restrict__ Win,
    const float* __restrict__ bin_,
    const float* __restrict__ g1, const float* __restrict__ be1)
{
    __shared__ float x[88];
    __shared__ float sc1s[64], sh1s[64];
    __shared__ float r1[128], r2[128];
    int b = blockIdx.x, k = threadIdx.x;

    // BN1 finalize (every block, identical deterministic result)
    {
        int col = k & 63, part = k >> 6;
        float s = 0.f, s2 = 0.f;
        for (int q = part; q < 128; q += 2) {
            s += g_part[q * 64 + col];
            s2 += g_part2[q * 64 + col];
        }
        r1[k] = s; r2[k] = s2;
        __syncthreads();
        if (k < 64) {
            s = r1[k] + r1[k + 64];
            s2 = r2[k] + r2[k + 64];
            float m = s * (1.f / 2048.f);
            float v = s2 * (1.f / 2048.f) - m * m;
            float sc = g1[k] * rsqrtf(v + 1e-5f);
            sc1s[k] = sc;
            sh1s[k] = be1[k] - m * sc;
        }
        __syncthreads();
    }

    int row = (b < 128) ? (15 * 128 + b) : ((b - 128) * 128 + 0);
    if (k < 15)      x[k] = ops[row * 15 + k];
    else if (k < 22) x[k] = ext[row * 7 + (k - 15)];
    else if (k < 24) x[k] = card[row * 2 + (k - 22)];
    else if (k < 88) x[k] = g_lo[(size_t)row * 64 + (k - 24)] * sc1s[k - 24] + sh1s[k - 24];
    __syncthreads();

    if (b < 128) {
        float gi = b2[k], gg = b2[256 + k], go = b2[384 + k];
        for (int j = 0; j < 88; j++) {
            float xv = x[j];
            const float* w = Wih2 + j * 512;
            gi += xv * w[k];
            gg += xv * w[256 + k];
            go += xv * w[384 + k];
        }
        float c = sigf(gi) * tanh_(gg);  // sig(f)*c_prev = 0
        float h = sigf(go) * tanh_(c);
        g_h[0][b * 128 + k] = h;
        g_c[0][b * 128 + k] = c;
    } else {
        int l = b - 128;
        float s = bin_[k];
        for (int j = 0; j < 88; j++) s += x[j] * Win[j * 128 + k];
        g_base[(14 - l) * 128 + k] = s;
    }
}

// ---------------------------------------------------------------------------
// K4: fused tree scan — 15 steps, persistent. grid (8,5)=40 blocks, block 512.
// Full 256x128 W slice staged once into smem.  q = tid>>7 (k quarter of 64),
// warp4 rows r0=warp4*4, lane cols lane*4.
// smem (floats): Wsm 32768 | A[16][264] 4224 | red 3*2048 = 43136 f = 172544 B.
// ---------------------------------------------------------------------------
__global__ void __launch_bounds__(512) tree_kernel(const int* __restrict__ mapping)
{
    const unsigned int NB = 40;
    extern __shared__ float smem[];
    float* Wsm = smem;
    float (*A)[264] = (float (*)[264])(smem + 32768);
    float* red = smem + 36992;
    uint32_t wsm_addr = (uint32_t)__cvta_generic_to_shared(Wsm);

    int tid = threadIdx.x, bx = blockIdx.x, g = blockIdx.y;
    int bid = g * 8 + bx;

    // stage W slice: Wsm[k][c] = g_Wcat[k*640 + g*128 + c]; row = 32 x 16B
    for (int i = tid; i < 8192; i += 512)
        cpasync16(wsm_addr + i * 16,
                  g_Wcat + (size_t)(i >> 5) * 640 + g * 128 + (i & 31) * 4);
    cp_commit();
    cp_wait0();
    __syncthreads();

    const int q = tid >> 7, t128 = tid & 127;
    const int warp4 = t128 >> 5, lane = t128 & 31;
    const int r0 = warp4 * 4;
    const int k0 = q * 64;
    const ulonglong2* Wu2 = (const ulonglong2*)Wsm;

    for (int s = 0; s < 15; s++) {
        int lvl = 14 - s, p = s & 1;
        const float* __restrict__ hprev = g_h[p];

        // gather A = [lh|rh] rows for this block's 16 n
        for (int i = tid; i < 16 * 256; i += 512) {
            int r = i >> 8, h = i & 255;
            int n = bx * 16 + r;
            int mp = mapping[(lvl * 128 + n) * 2 + (h >> 7)];
            A[r][h] = (mp > 0) ? hprev[(mp - 1) * 128 + (h & 127)] : 0.f;
        }
        __syncthreads();

        unsigned long long acc[8];
#pragma unroll
        for (int j = 0; j < 8; j++) acc[j] = 0ull;

#pragma unroll 4
        for (int kk4 = 0; kk4 < 16; kk4++) {
            float4 a4[4];
#pragma unroll
            for (int r = 0; r < 4; r++)
                a4[r] = *(const float4*)&A[r0 + r][k0 + kk4 * 4];
#pragma unroll
            for (int qq = 0; qq < 4; qq++) {
                int k = k0 + kk4 * 4 + qq;
                ulonglong2 w = Wu2[k * 32 + lane];
#pragma unroll
                for (int r = 0; r < 4; r++) {
                    float av = (qq == 0) ? a4[r].x : (qq == 1) ? a4[r].y
                             : (qq == 2) ? a4[r].z : a4[r].w;
                    unsigned long long v = dup2(av);
                    fma2(acc[r * 2], v, w.x);
                    fma2(acc[r * 2 + 1], v, w.y);
                }
            }
        }

        if (q > 0) {
#pragma unroll
            for (int r = 0; r < 4; r++)
                *(ulonglong2*)&red[(q - 1) * 2048 + (r0 + r) * 128 + lane * 4] =
                    make_ulonglong2(acc[r * 2], acc[r * 2 + 1]);
        }
        __syncthreads();
        if (q == 0) {
#pragma unroll
            for (int r = 0; r < 4; r++) {
#pragma unroll
                for (int j = 0; j < 3; j++) {
                    ulonglong2 p2 = *(const ulonglong2*)&red[j * 2048 + (r0 + r) * 128 + lane * 4];
                    add2(acc[r * 2], p2.x);
                    add2(acc[r * 2 + 1], p2.y);
                }
                *(ulonglong2*)(g_P + (size_t)(bx * 16 + r0 + r) * 640 + g * 128 + lane * 4) =
                    make_ulonglong2(acc[r * 2], acc[r * 2 + 1]);
            }
        }

        grid_barrier(NB);

        // pointwise cell update over 128x128 elems, 20480 threads
        for (int idx = bid * 512 + tid; idx < 16384; idx += 20480) {
            int n = idx >> 7, k = idx & 127;
            int mp0 = mapping[(lvl * 128 + n) * 2 + 0];
            int mp1 = mapping[(lvl * 128 + n) * 2 + 1];
            float lc = (mp0 > 0) ? g_c[p][(mp0 - 1) * 128 + k] : 0.f;
            float rc = (mp1 > 0) ? g_c[p][(mp1 - 1) * 128 + k] : 0.f;
            float bse = g_base[s * 128 + k];
            const float* P = g_P + (size_t)n * 640;
            float pre[5];
#pragma unroll
            for (int qq = 0; qq < 5; qq++)
                pre[qq] = bse + P[qq * 128 + k] + g_bb[qq * 128 + k];
            float i = sigf(pre[0]), lf = sigf(pre[1]), rf = sigf(pre[2]);
            float u = tanh_(pre[3]), o = sigf(pre[4]);
            float c = i * u + lf * lc + rf * rc;
            g_c[1 - p][n * 128 + k] = c;
            g_h[1 - p][n * 128 + k] = o * tanh_(c);
        }

        grid_barrier(NB);
    }
}

// ---------------------------------------------------------------------------
// K5: fused tail: BN2 -> t1 -> BN3 -> t2 -> sigmoid output.  One block, 256.
// ---------------------------------------------------------------------------
__global__ void __launch_bounds__(256) tail_kernel(
    const float* __restrict__ g2, const float* __restrict__ be2,
    const float* __restrict__ Wt1, const float* __restrict__ bt1,
    const float* __restrict__ g3, const float* __restrict__ be3,
    const float* __restrict__ Wt2, const float* __restrict__ bt2,
    const float* __restrict__ Wo, const float* __restrict__ bo,
    float* __restrict__ out)
{
    __shared__ float t1s[128 * 64];  // 32KB
    __shared__ float sc[128], sh[128];
    __shared__ float red[256], red2[256];
    int tid = threadIdx.x;

    // BN2 stats over g_h[1] (128x128)
    {
        int col = tid & 127, part = tid >> 7;
        float s = 0.f, s2 = 0.f;
        for (int r = part; r < 128; r += 2) {
            float v = g_h[1][r * 128 + col];
            s += v; s2 += v * v;
        }
        red[tid] = s; red2[tid] = s2;
        __syncthreads();
        if (tid < 128) {
            s = red[tid] + red[tid + 128];
            s2 = red2[tid] + red2[tid + 128];
            float m = s * (1.f / 128.f);
            float v = s2 * (1.f / 128.f) - m * m;
            float scl = g2[tid] * rsqrtf(v + 1e-5f);
            sc[tid] = scl;
            sh[tid] = be2[tid] - m * scl;
        }
        __syncthreads();
    }

    // t1 = relu(bn2(h) @ Wt1 + bt1)  (128x64)
    for (int o = tid; o < 8192; o += 256) {
        int n = o >> 6, j = o & 63;
        float acc = bt1[j];
        for (int h = 0; h < 128; h++)
            acc += (g_h[1][n * 128 + h] * sc[h] + sh[h]) * Wt1[h * 64 + j];
        t1s[o] = fmaxf(acc, 0.f);
    }
    __syncthreads();

    // BN3 stats over t1s (128x64)
    {
        int col = tid & 63, part = tid >> 6;
        float s = 0.f, s2 = 0.f;
        for (int r = part; r < 128; r += 4) {
            float v = t1s[r * 64 + col];
            s += v; s2 += v * v;
        }
        red[tid] = s; red2[tid] = s2;
        __syncthreads();
        if (tid < 64) {
            for (int p = 1; p < 4; p++) { s += red[tid + 64 * p]; s2 += red2[tid + 64 * p]; }
            float m = s * (1.f / 128.f);
            float v = s2 * (1.f / 128.f) - m * m;
            float scl = g3[tid] * rsqrtf(v + 1e-5f);
            sc[tid] = scl;
            sh[tid] = be3[tid] - m * scl;
        }
        __syncthreads();
    }

    // t2 = relu(bn3(t1)@Wt2+bt2); out = sigmoid(t2@Wo+bo)
    if (tid < 128) {
        int n = tid;
        float tn[64];
#pragma unroll
        for (int i = 0; i < 64; i++) tn[i] = t1s[n * 64 + i] * sc[i] + sh[i];
        float a = bo[0];
        for (int j = 0; j < 64; j++) {
            float s = bt2[j];
#pragma unroll
            for (int i = 0; i < 64; i++) s += tn[i] * Wt2[i * 64 + j];
            a += fmaxf(s, 0.f) * Wo[j];
        }
        out[n] = sigf(a);
    }
}

// ---------------------------------------------------------------------------
extern "C" void kernel_launch(void* const* d_in, const int* in_sizes, int n_in,
                              void* d_out, int out_size)
{
    const float* operators = (const float*)d_in[0];
    const float* extra     = (const float*)d_in[1];
    const float* card      = (const float*)d_in[2];
    const float* cond1     = (const float*)d_in[3];
    const float* cond2     = (const float*)d_in[4];
    const int*   mapping   = (const int*)  d_in[5];
    const float* Wih1      = (const float*)d_in[6];
    const float* Whh1      = (const float*)d_in[7];
    const float* b1        = (const float*)d_in[8];
    const float* Wc        = (const float*)d_in[9];
    const float* bc        = (const float*)d_in[10];
    const float* g1        = (const float*)d_in[11];
    const float* be1       = (const float*)d_in[12];
    const float* Wih2      = (const float*)d_in[13];
    // d_in[14] = Whh2: unused (single step from zero state)
    const float* b2        = (const float*)d_in[15];
    const float* Win       = (const float*)d_in[16];
    const float* bin_      = (const float*)d_in[17];
    const float* Wlh       = (const float*)d_in[18];
    const float* blh       = (const float*)d_in[19];
    const float* Wrh       = (const float*)d_in[20];
    const float* brh       = (const float*)d_in[21];
    const float* g2        = (const float*)d_in[22];
    const float* be2       = (const float*)d_in[23];
    const float* Wt1       = (const float*)d_in[24];
    const float* bt1       = (const float*)d_in[25];
    const float* g3        = (const float*)d_in[26];
    const float* be3       = (const float*)d_in[27];
    const float* Wt2       = (const float*)d_in[28];
    const float* bt2       = (const float*)d_in[29];
    const float* Wo        = (const float*)d_in[30];
    const float* bo        = (const float*)d_in[31];
    float* out = (float*)d_out;

    const int LSTM1_SMEM = 52736 * 4;   // 210944 B
    const int TREE_SMEM  = 43136 * 4;   // 172544 B
    cudaFuncSetAttribute(lstm1_kernel,
                         cudaFuncAttributeMaxDynamicSharedMemorySize, LSTM1_SMEM);
    cudaFuncSetAttribute(tree_kernel,
                         cudaFuncAttributeMaxDynamicSharedMemorySize, TREE_SMEM);

    // 5 launches; tree at our idx 3 so ncu (-s 5) profiles it this round.
    lstm1_kernel<<<128, 512, LSTM1_SMEM>>>(cond1, cond2, Wih1, Whh1, b1,
                                           Wlh, Wrh, blh, brh);
    lo_kernel<<<128, 256>>>(Wc, bc);
    prep_kernel<<<143, 128>>>(operators, extra, card, Wih2, b2, Win, bin_, g1, be1);
    tree_kernel<<<dim3(8, 5), 512, TREE_SMEM>>>(mapping);
    tail_kernel<<<1, 256>>>(g2, be2, Wt1, bt1, g3, be3, Wt2, bt2, Wo, bo, out);
}